// round 8
// baseline (speedup 1.0000x reference)
#include <cuda_runtime.h>
#include <cuda_bf16.h>
#include <cstdint>
#include <math.h>

#define BB 16
#define NN 1024
#define DD 512
#define ROWS (BB*NN)          // 16384
#define TIME_STEP 3

// ---------------- fp32 scratch ----------------
__device__ float g_nodes[BB*NN*DD];
__device__ float g_u3   [BB*NN*DD];          // u3, then zv
__device__ float g_t    [BB*NN*DD];          // (rv*f)@w5u^T
__device__ float g_gates[BB*NN*3*DD];        // [16384][1536]

// ---------------- bf16 hi/lo operand buffers ----------------
__device__ __nv_bfloat16 g_inM_h [NN*NN], g_inM_l [NN*NN];
__device__ __nv_bfloat16 g_outM_h[NN*NN], g_outM_l[NN*NN];
__device__ __nv_bfloat16 g_wcat_h[3*DD*2*DD], g_wcat_l[3*DD*2*DD];  // [1536][1024]
__device__ __nv_bfloat16 g_w3u_h[DD*DD],   g_w3u_l[DD*DD];
__device__ __nv_bfloat16 g_w5u_h[DD*DD],   g_w5u_l[DD*DD];
__device__ __nv_bfloat16 g_ndT_h[BB*DD*NN], g_ndT_l[BB*DD*NN];   // [b][d][n]
__device__ __nv_bfloat16 g_ndb_h[BB*NN*DD], g_ndb_l[BB*NN*DD];   // [b][n][d]
__device__ __nv_bfloat16 g_ain_h[BB*NN*DD], g_ain_l[BB*NN*DD];
__device__ __nv_bfloat16 g_aout_h[BB*NN*DD], g_aout_l[BB*NN*DD];
__device__ __nv_bfloat16 g_rf_h [BB*NN*DD], g_rf_l [BB*NN*DD];

// ---------------- helpers ----------------
__device__ __forceinline__ uint32_t smem_u32(const void* p) {
    uint32_t a;
    asm("{ .reg .u64 t; cvta.to.shared.u64 t, %1; cvt.u32.u64 %0, t; }" : "=r"(a) : "l"(p));
    return a;
}
__device__ __forceinline__ void split2(float x, float y, uint32_t& hi, uint32_t& lo) {
    __nv_bfloat162 h = __floats2bfloat162_rn(x, y);   // low=x, high=y
    float rx = x - __bfloat162float(__low2bfloat16(h));
    float ry = y - __bfloat162float(__high2bfloat16(h));
    __nv_bfloat162 l = __floats2bfloat162_rn(rx, ry);
    hi = *(uint32_t*)&h; lo = *(uint32_t*)&l;
}
__device__ __forceinline__ void cpa16(uint32_t s, const void* g) {
    asm volatile("cp.async.cg.shared.global [%0], [%1], 16;" :: "r"(s), "l"(g));
}
__device__ __forceinline__ void cpa_commit() {
    asm volatile("cp.async.commit_group;" ::: "memory");
}
__device__ __forceinline__ void cpa_wait1() {
    asm volatile("cp.async.wait_group 1;" ::: "memory");
}
__device__ __forceinline__ void ldm_x4(uint32_t* r, uint32_t addr) {
    asm volatile("ldmatrix.sync.aligned.m8n8.x4.shared.b16 {%0,%1,%2,%3}, [%4];"
                 : "=r"(r[0]), "=r"(r[1]), "=r"(r[2]), "=r"(r[3]) : "r"(addr));
}
__device__ __forceinline__ void mma_bf16(float* d, const uint32_t* a, const uint32_t* b) {
    asm volatile("mma.sync.aligned.m16n8k16.row.col.f32.bf16.bf16.f32 "
                 "{%0,%1,%2,%3}, {%4,%5,%6,%7}, {%8,%9}, {%0,%1,%2,%3};"
                 : "+f"(d[0]), "+f"(d[1]), "+f"(d[2]), "+f"(d[3])
                 : "r"(a[0]), "r"(a[1]), "r"(a[2]), "r"(a[3]), "r"(b[0]), "r"(b[1]));
}

// ======================= bf16x3 mma.sync GEMM (256x128 CTA, 512 thr) ==========
// C[m][n] = sum_k A'[m][k]*B[n][k]; A,B pre-split bf16 hi/lo, k-major.
// msel=0: A' = A for k<ksplit else A2 at k-ksplit; batch z via aB/bB/cB/coB.
// msel=1: matrix pair (A vs A2) chosen by z>=16; batch = z&15; epilogue goes
//         to (Coh,Col) for z<16 and (Co2h,Co2l) for z>=16. ksplit unused.
#define KC 32
#define RS 40                      // smem row stride in halves (80B, 16B-aligned)
#define TM 256
#define TN 128
#define A_HB (TM*RS)               // A tile halves (10240)
#define B_HB (TN*RS)               // B tile halves (5120)
#define STAGE_HB (2*A_HB + 2*B_HB) // Ahi|Alo|Bhi|Blo = 30720 halves
#define NSTAGE 3
#define GEMM_SMEM (NSTAGE*STAGE_HB*2)   // 184320 bytes
#define NT 512

__device__ __forceinline__ void load_tileA(uint32_t sbase, const __nv_bfloat16* g,
                                           int ld, int tid)
{
    int row = tid >> 2, cb = tid & 3;
    cpa16(sbase + (uint32_t)(row*RS + cb*8)*2, g + (long)row*ld + cb*8);
    cpa16(sbase + (uint32_t)((row+128)*RS + cb*8)*2, g + (long)(row+128)*ld + cb*8);
}
__device__ __forceinline__ void load_tileB(uint32_t sbase, const __nv_bfloat16* g,
                                           int ld, int tid)
{
    int row = tid >> 2, cb = tid & 3;
    cpa16(sbase + (uint32_t)(row*RS + cb*8)*2, g + (long)row*ld + cb*8);
}

__global__ __launch_bounds__(NT, 1)
void gemm_mma(const __nv_bfloat16* __restrict__ Ah, const __nv_bfloat16* __restrict__ Al,
              const __nv_bfloat16* __restrict__ A2h, const __nv_bfloat16* __restrict__ A2l,
              int ksplit, int lda, int msel,
              const __nv_bfloat16* __restrict__ Bh, const __nv_bfloat16* __restrict__ Bl,
              int ldb,
              float* __restrict__ C, int ldc,
              __nv_bfloat16* __restrict__ Coh, __nv_bfloat16* __restrict__ Col,
              __nv_bfloat16* __restrict__ Co2h, __nv_bfloat16* __restrict__ Co2l,
              int ldco,
              int Kd, long aB, long bB, long cB, long coB)
{
    extern __shared__ char smem[];
    const uint32_t sb = smem_u32(smem);

    long z = blockIdx.z;
    if (msel) {
        if (z >= 16) { Ah = A2h; Al = A2l; Coh = Co2h; Col = Co2l; z -= 16; }
        A2h = Ah; A2l = Al;
        ksplit = 1 << 30;
    }
    Ah += z*aB; Al += z*aB; A2h += z*aB; A2l += z*aB;
    Bh += z*bB; Bl += z*bB;
    if (C)   C   += z*cB;
    if (Coh) { Coh += z*coB; Col += z*coB; }

    const int tid = threadIdx.x;
    const int wid = tid >> 5, lane = tid & 31;
    const int m0 = blockIdx.y * TM, n0 = blockIdx.x * TN;
    const int wrow = (wid & 3) * 64;       // 4 warp-rows x 64
    const int wcol = (wid >> 2) * 32;      // 4 warp-cols x 32

    float acc[4][4][4];                    // [mb][nb][frag] : 64x32 warp tile
    #pragma unroll
    for (int i = 0; i < 4; i++)
        #pragma unroll
        for (int j = 0; j < 4; j++)
            #pragma unroll
            for (int k = 0; k < 4; k++) acc[i][j][k] = 0.f;

    const int KT = Kd / KC;

    auto load_stage = [&](int t) {
        int kbase = t * KC;
        const __nv_bfloat16 *pah = Ah, *pal = Al;
        int ka = kbase;
        if (kbase >= ksplit) { pah = A2h; pal = A2l; ka -= ksplit; }
        uint32_t s = sb + (uint32_t)(t % NSTAGE) * STAGE_HB * 2;
        load_tileA(s,                   pah + (long)m0*lda + ka,    lda, tid);
        load_tileA(s + A_HB*2,          pal + (long)m0*lda + ka,    lda, tid);
        load_tileB(s + 2*A_HB*2,        Bh  + (long)n0*ldb + kbase, ldb, tid);
        load_tileB(s + 2*A_HB*2 + B_HB*2, Bl + (long)n0*ldb + kbase, ldb, tid);
    };

    load_stage(0); cpa_commit();
    load_stage(1); cpa_commit();

    const int ar = lane & 15, acg = lane >> 4;
    const int bg = lane >> 3, bl8 = lane & 7;

    for (int t = 0; t < KT; t++) {
        cpa_wait1();          // stage t complete (<=1 newer group pending)
        __syncthreads();      // publish stage t; all warps done with stage t-1
        if (t + 2 < KT) load_stage(t + 2);   // overwrites buffer (t-1)%3: safe
        cpa_commit();         // keep group accounting uniform

        const uint32_t s = sb + (uint32_t)(t % NSTAGE) * STAGE_HB * 2;
        const uint32_t sAh = s, sAl = s + A_HB*2;
        const uint32_t sBh = s + 2*A_HB*2, sBl = sBh + B_HB*2;

        #pragma unroll
        for (int ks = 0; ks < 2; ks++) {
            uint32_t bh[2][4], bl[2][4];
            #pragma unroll
            for (int nb2 = 0; nb2 < 2; nb2++) {
                int rowb = wcol + nb2*16 + ((bg >> 1) & 1)*8 + bl8;
                int kcb  = ks*16 + (bg & 1)*8;
                uint32_t off = (uint32_t)(rowb*RS + kcb)*2;
                ldm_x4(bh[nb2], sBh + off);
                ldm_x4(bl[nb2], sBl + off);
            }
            #pragma unroll
            for (int mb = 0; mb < 4; mb++) {
                uint32_t ah[4], al[4];
                uint32_t off = (uint32_t)((wrow + mb*16 + ar)*RS + ks*16 + acg*8)*2;
                ldm_x4(ah, sAh + off);
                ldm_x4(al, sAl + off);
                #pragma unroll
                for (int nb = 0; nb < 4; nb++) {
                    const uint32_t* ph = &bh[nb >> 1][(nb & 1)*2];
                    const uint32_t* pl = &bl[nb >> 1][(nb & 1)*2];
                    mma_bf16(acc[mb][nb], ah, ph);
                    mma_bf16(acc[mb][nb], ah, pl);
                    mma_bf16(acc[mb][nb], al, ph);
                }
            }
        }
    }

    // ---- epilogue ----
    const int r0 = lane >> 2, c0 = (lane & 3)*2;
    #pragma unroll
    for (int mb = 0; mb < 4; mb++) {
        #pragma unroll
        for (int nb = 0; nb < 4; nb++) {
            long row = m0 + wrow + mb*16 + r0;
            int  col = n0 + wcol + nb*8 + c0;
            float* a = acc[mb][nb];
            if (C) {
                *(float2*)&C[row*ldc + col]     = make_float2(a[0], a[1]);
                *(float2*)&C[(row+8)*ldc + col] = make_float2(a[2], a[3]);
            }
            if (Coh) {
                uint32_t hi, lo;
                split2(a[0], a[1], hi, lo);
                *(uint32_t*)&Coh[row*ldco + col] = hi;
                *(uint32_t*)&Col[row*ldco + col] = lo;
                split2(a[2], a[3], hi, lo);
                *(uint32_t*)&Coh[(row+8)*ldco + col] = hi;
                *(uint32_t*)&Col[(row+8)*ldco + col] = lo;
            }
        }
    }
}

// ---------------- fused one-time converter ----------------
__global__ void cvt_all(const float* __restrict__ in_m, const float* __restrict__ out_m,
                        const float* __restrict__ w3w, const float* __restrict__ w4w,
                        const float* __restrict__ w5w, const float* __restrict__ w3u,
                        const float* __restrict__ w5u)
{
    long p = ((long)blockIdx.x*blockDim.x + threadIdx.x) * 2;
    const long S0 = 1048576, S1 = 2097152, S2 = S1 + 524288, S3 = S2 + 524288,
               S4 = S3 + 524288, S5 = S4 + 262144, S6 = S5 + 262144;
    if (p >= S6) return;
    const float* src; __nv_bfloat16 *dh, *dl; long off;
    if      (p < S0) { src = in_m;  dh = g_inM_h;  dl = g_inM_l;  off = p; }
    else if (p < S1) { src = out_m; dh = g_outM_h; dl = g_outM_l; off = p - S0; }
    else if (p < S2) { src = w3w; dh = g_wcat_h;           dl = g_wcat_l;           off = p - S1; }
    else if (p < S3) { src = w4w; dh = g_wcat_h + 524288;  dl = g_wcat_l + 524288;  off = p - S2; }
    else if (p < S4) { src = w5w; dh = g_wcat_h + 1048576; dl = g_wcat_l + 1048576; off = p - S3; }
    else if (p < S5) { src = w3u; dh = g_w3u_h; dl = g_w3u_l; off = p - S4; }
    else             { src = w5u; dh = g_w5u_h; dl = g_w5u_l; off = p - S5; }
    float2 v = *(const float2*)&src[off];
    uint32_t h, l;
    split2(v.x, v.y, h, l);
    *(uint32_t*)&dh[off] = h;
    *(uint32_t*)&dl[off] = l;
}

// nodes [b][n][d] fp32 -> ndb hi/lo (straight) + ndT hi/lo (transposed [b][d][n])
__global__ void transpose_cvt(const float* __restrict__ src)
{
    __shared__ float tile[32][33];
    const int b = blockIdx.z;
    const int d0 = blockIdx.x*32, n0 = blockIdx.y*32;
    const float* s = src + (long)b*NN*DD;
    const int tid = threadIdx.x;
    #pragma unroll
    for (int i = 0; i < 4; i++) {
        int p = tid + i*256, n = p >> 5, d = p & 31;
        tile[n][d] = s[(long)(n0+n)*DD + d0 + d];
    }
    __syncthreads();
    #pragma unroll
    for (int i = 0; i < 2; i++) {
        int p = tid + i*256, n = p >> 4, dp = p & 15;
        uint32_t h, l;
        split2(tile[n][dp*2], tile[n][dp*2+1], h, l);
        long o = ((long)b*NN + n0 + n)*DD + d0 + dp*2;
        *(uint32_t*)&g_ndb_h[o] = h; *(uint32_t*)&g_ndb_l[o] = l;
    }
    #pragma unroll
    for (int i = 0; i < 2; i++) {
        int p = tid + i*256, d = p >> 4, np = p & 15;
        uint32_t h, l;
        split2(tile[np*2][d], tile[np*2+1][d], h, l);
        long o = ((long)b*DD + d0 + d)*NN + n0 + np*2;
        *(uint32_t*)&g_ndT_h[o] = h; *(uint32_t*)&g_ndT_l[o] = l;
    }
}

// ---------------- elementwise ----------------
__global__ void elem1(const float* __restrict__ b3w, const float* __restrict__ b3u,
                      const float* __restrict__ b4w)
{
    int p = blockIdx.x*blockDim.x + threadIdx.x;
    long i = (long)p*2;
    int row = (int)(i >> 9), e = (int)(i & 511);
    float2 u = *(const float2*)&g_u3[i];
    float2 f = *(const float2*)&g_nodes[i];
    float g3a = g_gates[(long)row*1536 + e],       g3b = g_gates[(long)row*1536 + e + 1];
    float g4a = g_gates[(long)row*1536 + 512 + e], g4b = g_gates[(long)row*1536 + 512 + e + 1];
    float ua = u.x + b3u[e], ub = u.y + b3u[e+1];
    float za = 1.f/(1.f + expf(-(g3a + b3w[e] + ua)));
    float zb = 1.f/(1.f + expf(-(g3b + b3w[e+1] + ub)));
    float ra = 1.f/(1.f + expf(-(g4a + b4w[e] + ua)));
    float rb = 1.f/(1.f + expf(-(g4b + b4w[e+1] + ub)));
    *(float2*)&g_u3[i] = make_float2(za, zb);
    uint32_t h, l;
    split2(ra*f.x, rb*f.y, h, l);
    *(uint32_t*)&g_rf_h[i] = h;
    *(uint32_t*)&g_rf_l[i] = l;
}

__global__ void elem2(const float* __restrict__ b5w, const float* __restrict__ b5u)
{
    long i = (long)blockIdx.x*blockDim.x + threadIdx.x;
    int row = (int)(i >> 9), e = (int)(i & 511);
    float t  = g_t[i];
    float g5 = g_gates[(long)row*1536 + 1024 + e];
    float hv = tanhf(g5 + b5w[e] + t + b5u[e]);
    float z  = g_u3[i];
    float f  = g_nodes[i];
    g_nodes[i] = (1.f - z)*f + z*hv;
}

__global__ void copy4(const float4* __restrict__ src, float4* __restrict__ dst, int n4)
{
    int i = blockIdx.x*blockDim.x + threadIdx.x;
    if (i < n4) dst[i] = src[i];
}

// ---------------- host launcher ----------------
extern "C" void kernel_launch(void* const* d_in, const int* in_sizes, int n_in,
                              void* d_out, int out_size)
{
    (void)in_sizes; (void)n_in; (void)out_size;
    const float* x     = (const float*)d_in[0];
    const float* in_m  = (const float*)d_in[1];
    const float* out_m = (const float*)d_in[2];
    const float* w3w   = (const float*)d_in[3];
    const float* b3w   = (const float*)d_in[4];
    const float* w3u   = (const float*)d_in[5];
    const float* b3u   = (const float*)d_in[6];
    const float* w4w   = (const float*)d_in[7];
    const float* b4w   = (const float*)d_in[8];
    const float* w5w   = (const float*)d_in[9];
    const float* b5w   = (const float*)d_in[10];
    const float* w5u   = (const float*)d_in[11];
    const float* b5u   = (const float*)d_in[12];
    float* out = (float*)d_out;

    float *nodes, *u3, *tt, *gates;
    cudaGetSymbolAddress((void**)&nodes, g_nodes);
    cudaGetSymbolAddress((void**)&u3,    g_u3);
    cudaGetSymbolAddress((void**)&tt,    g_t);
    cudaGetSymbolAddress((void**)&gates, g_gates);

    __nv_bfloat16 *inMh,*inMl,*outMh,*outMl,*wcath,*wcatl;
    __nv_bfloat16 *w3uh,*w3ul,*w5uh,*w5ul,*ndTh,*ndTl,*ndbh,*ndbl;
    __nv_bfloat16 *ainh,*ainl,*aouth,*aoutl,*rfh,*rfl;
    cudaGetSymbolAddress((void**)&inMh, g_inM_h);  cudaGetSymbolAddress((void**)&inMl, g_inM_l);
    cudaGetSymbolAddress((void**)&outMh,g_outM_h); cudaGetSymbolAddress((void**)&outMl,g_outM_l);
    cudaGetSymbolAddress((void**)&wcath,g_wcat_h); cudaGetSymbolAddress((void**)&wcatl,g_wcat_l);
    cudaGetSymbolAddress((void**)&w3uh, g_w3u_h);  cudaGetSymbolAddress((void**)&w3ul, g_w3u_l);
    cudaGetSymbolAddress((void**)&w5uh, g_w5u_h);  cudaGetSymbolAddress((void**)&w5ul, g_w5u_l);
    cudaGetSymbolAddress((void**)&ndTh, g_ndT_h);  cudaGetSymbolAddress((void**)&ndTl, g_ndT_l);
    cudaGetSymbolAddress((void**)&ndbh, g_ndb_h);  cudaGetSymbolAddress((void**)&ndbl, g_ndb_l);
    cudaGetSymbolAddress((void**)&ainh, g_ain_h);  cudaGetSymbolAddress((void**)&ainl, g_ain_l);
    cudaGetSymbolAddress((void**)&aouth,g_aout_h); cudaGetSymbolAddress((void**)&aoutl,g_aout_l);
    cudaGetSymbolAddress((void**)&rfh,  g_rf_h);   cudaGetSymbolAddress((void**)&rfl,  g_rf_l);

    cudaFuncSetAttribute(gemm_mma, cudaFuncAttributeMaxDynamicSharedMemorySize, GEMM_SMEM);

    const long ND = (long)NN*DD;     // 524288
    const int  BIG = 1 << 30;

    copy4<<<(BB*NN*DD/4 + 255)/256, 256>>>((const float4*)x, (float4*)nodes, BB*NN*DD/4);
    cvt_all<<<8192, 256>>>(in_m, out_m, w3w, w4w, w5w, w3u, w5u);

    for (int step = 0; step < TIME_STEP; step++) {
        transpose_cvt<<<dim3(DD/32, NN/32, BB), 256>>>(nodes);

        // fused a_in + a_out: M=1024, N=512, K=1024, z=0..31 (z>=16 -> out_matrix)
        dim3 gp(DD/TN, NN/TM, 2*BB);        // (4, 4, 32)
        gemm_mma<<<gp, NT, GEMM_SMEM>>>(inMh, inMl, outMh, outMl, BIG, NN, 1,
                                        ndTh, ndTl, NN,
                                        nullptr, 0,
                                        ainh, ainl, aouth, aoutl, DD,
                                        NN, 0L, ND, 0L, ND);

        // fused gates: [ain|aout] @ wcat^T, M=16384, N=1536, K=1024 (split at 512)
        dim3 gg3(3*DD/TN, ROWS/TM, 1);      // (12, 64)
        gemm_mma<<<gg3, NT, GEMM_SMEM>>>(ainh, ainl, aouth, aoutl, DD, DD, 0,
                                         wcath, wcatl, 2*DD,
                                         gates, 3*DD,
                                         nullptr, nullptr, nullptr, nullptr, 0,
                                         2*DD, 0L, 0L, 0L, 0L);

        // u3 = nodes @ w3u^T, M=16384, N=512, K=512
        dim3 gg(DD/TN, ROWS/TM, 1);         // (4, 64)
        gemm_mma<<<gg, NT, GEMM_SMEM>>>(ndbh, ndbl, ndbh, ndbl, BIG, DD, 0,
                                        w3uh, w3ul, DD,
                                        u3, DD,
                                        nullptr, nullptr, nullptr, nullptr, 0,
                                        DD, 0L, 0L, 0L, 0L);

        elem1<<<ROWS*DD/2/256, 256>>>(b3w, b3u, b4w);

        // t = (rv*f) @ w5u^T
        gemm_mma<<<gg, NT, GEMM_SMEM>>>(rfh, rfl, rfh, rfl, BIG, DD, 0,
                                        w5uh, w5ul, DD,
                                        tt, DD,
                                        nullptr, nullptr, nullptr, nullptr, 0,
                                        DD, 0L, 0L, 0L, 0L);

        elem2<<<ROWS*DD/256, 256>>>(b5w, b5u);
    }

    copy4<<<(BB*NN*DD/4 + 255)/256, 256>>>((const float4*)nodes, (float4*)out, BB*NN*DD/4);
    copy4<<<(NN*NN/4 + 255)/256, 256>>>((const float4*)in_m,
                                        (float4*)(out + (long)BB*NN*DD), NN*NN/4);
}

// round 11
// speedup vs baseline: 1.5074x; 1.5074x over previous
#include <cuda_runtime.h>
#include <cuda_bf16.h>
#include <cstdint>
#include <math.h>

#define BB 16
#define NN 1024
#define DD 512
#define ROWS (BB*NN)          // 16384
#define TIME_STEP 3

// ---------------- fp32 scratch ----------------
__device__ float g_nodes[BB*NN*DD];
__device__ float g_u3   [BB*NN*DD];          // u3, then zv
__device__ float g_t    [BB*NN*DD];          // (rv*f)@w5u^T
__device__ float g_gates[BB*NN*3*DD];        // [16384][1536]

// ---------------- bf16 hi/lo operand buffers ----------------
__device__ __nv_bfloat16 g_inM_h [NN*NN], g_inM_l [NN*NN];
__device__ __nv_bfloat16 g_outM_h[NN*NN], g_outM_l[NN*NN];
__device__ __nv_bfloat16 g_wcat_h[3*DD*2*DD], g_wcat_l[3*DD*2*DD];  // [1536][1024]
__device__ __nv_bfloat16 g_w3u_h[DD*DD],   g_w3u_l[DD*DD];
__device__ __nv_bfloat16 g_w5u_h[DD*DD],   g_w5u_l[DD*DD];
__device__ __nv_bfloat16 g_ndT_h[BB*DD*NN], g_ndT_l[BB*DD*NN];   // [b][d][n]
__device__ __nv_bfloat16 g_ndb_h[BB*NN*DD], g_ndb_l[BB*NN*DD];   // [b][n][d]
__device__ __nv_bfloat16 g_ain_h[BB*NN*DD], g_ain_l[BB*NN*DD];
__device__ __nv_bfloat16 g_aout_h[BB*NN*DD], g_aout_l[BB*NN*DD];
__device__ __nv_bfloat16 g_rf_h [BB*NN*DD], g_rf_l [BB*NN*DD];

// ---------------- helpers ----------------
__device__ __forceinline__ uint32_t smem_u32(const void* p) {
    uint32_t a;
    asm("{ .reg .u64 t; cvta.to.shared.u64 t, %1; cvt.u32.u64 %0, t; }" : "=r"(a) : "l"(p));
    return a;
}
__device__ __forceinline__ void split2(float x, float y, uint32_t& hi, uint32_t& lo) {
    __nv_bfloat162 h = __floats2bfloat162_rn(x, y);   // low=x, high=y
    float rx = x - __bfloat162float(__low2bfloat16(h));
    float ry = y - __bfloat162float(__high2bfloat16(h));
    __nv_bfloat162 l = __floats2bfloat162_rn(rx, ry);
    hi = *(uint32_t*)&h; lo = *(uint32_t*)&l;
}
__device__ __forceinline__ void cpa16(uint32_t s, const void* g) {
    asm volatile("cp.async.cg.shared.global [%0], [%1], 16;" :: "r"(s), "l"(g));
}
__device__ __forceinline__ void cpa_commit() {
    asm volatile("cp.async.commit_group;" ::: "memory");
}
__device__ __forceinline__ void cpa_wait2() {
    asm volatile("cp.async.wait_group 2;" ::: "memory");
}
__device__ __forceinline__ void ldm_x4(uint32_t* r, uint32_t addr) {
    asm volatile("ldmatrix.sync.aligned.m8n8.x4.shared.b16 {%0,%1,%2,%3}, [%4];"
                 : "=r"(r[0]), "=r"(r[1]), "=r"(r[2]), "=r"(r[3]) : "r"(addr));
}
__device__ __forceinline__ void mma_bf16(float* d, const uint32_t* a, const uint32_t* b) {
    asm volatile("mma.sync.aligned.m16n8k16.row.col.f32.bf16.bf16.f32 "
                 "{%0,%1,%2,%3}, {%4,%5,%6,%7}, {%8,%9}, {%0,%1,%2,%3};"
                 : "+f"(d[0]), "+f"(d[1]), "+f"(d[2]), "+f"(d[3])
                 : "r"(a[0]), "r"(a[1]), "r"(a[2]), "r"(a[3]), "r"(b[0]), "r"(b[1]));
}

// ======================= bf16x3 mma.sync GEMM (128x128 CTA, 256 thr) ==========
// Warp grid 2 rows x 4 cols, warp tile 64x32.
// C[m][n] = sum_k A'[m][k]*B[n][k]; A,B pre-split bf16 hi/lo, k-major.
// msel=0: A' = A for k<ksplit else A2 at k-ksplit; batch z via aB/bB/cB/coB.
// msel=1: matrix pair (A vs A2) chosen by z>=16; batch = z&15; epilogue goes
//         to (Coh,Col) for z<16 and (Co2h,Co2l) for z>=16. ksplit unused.
#define KC 32
#define RS 40                      // smem row stride in halves (80B, 16B-aligned)
#define TILE_HB (128*RS)           // halves per tile
#define STAGE_HB (4*TILE_HB)       // Ahi|Alo|Bhi|Blo
#define NSTAGE 4
#define GEMM_SMEM (NSTAGE*STAGE_HB*2)   // 163840 bytes
#define NT 256

__device__ __forceinline__ void load_tile(uint32_t sbase, const __nv_bfloat16* g,
                                          int ld, int tid)
{
    int row = tid >> 2, cb = tid & 3;      // 256 threads: 2x 16B per tile
    cpa16(sbase + (uint32_t)(row*RS + cb*8)*2, g + (long)row*ld + cb*8);
    cpa16(sbase + (uint32_t)((row+64)*RS + cb*8)*2, g + (long)(row+64)*ld + cb*8);
}

__global__ __launch_bounds__(NT, 1)
void gemm_mma(const __nv_bfloat16* __restrict__ Ah, const __nv_bfloat16* __restrict__ Al,
              const __nv_bfloat16* __restrict__ A2h, const __nv_bfloat16* __restrict__ A2l,
              int ksplit, int lda, int msel,
              const __nv_bfloat16* __restrict__ Bh, const __nv_bfloat16* __restrict__ Bl,
              int ldb,
              float* __restrict__ C, int ldc,
              __nv_bfloat16* __restrict__ Coh, __nv_bfloat16* __restrict__ Col,
              __nv_bfloat16* __restrict__ Co2h, __nv_bfloat16* __restrict__ Co2l,
              int ldco,
              int Kd, long aB, long bB, long cB, long coB)
{
    extern __shared__ char smem[];
    const uint32_t sb = smem_u32(smem);

    long z = blockIdx.z;
    if (msel) {
        if (z >= 16) { Ah = A2h; Al = A2l; Coh = Co2h; Col = Co2l; z -= 16; }
        A2h = Ah; A2l = Al;
        ksplit = 1 << 30;
    }
    Ah += z*aB; Al += z*aB; A2h += z*aB; A2l += z*aB;
    Bh += z*bB; Bl += z*bB;
    if (C)   C   += z*cB;
    if (Coh) { Coh += z*coB; Col += z*coB; }

    const int tid = threadIdx.x;
    const int wid = tid >> 5, lane = tid & 31;
    const int m0 = blockIdx.y * 128, n0 = blockIdx.x * 128;
    const int wrow = (wid & 1) * 64;       // 2 warp-rows x 64
    const int wcol = (wid >> 1) * 32;      // 4 warp-cols x 32

    float acc[4][4][4];                    // [mb][nb][frag] : 64x32 warp tile
    #pragma unroll
    for (int i = 0; i < 4; i++)
        #pragma unroll
        for (int j = 0; j < 4; j++)
            #pragma unroll
            for (int k = 0; k < 4; k++) acc[i][j][k] = 0.f;

    const int KT = Kd / KC;

    auto load_stage = [&](int t) {
        int kbase = t * KC;
        const __nv_bfloat16 *pah = Ah, *pal = Al;
        int ka = kbase;
        if (kbase >= ksplit) { pah = A2h; pal = A2l; ka -= ksplit; }
        uint32_t s = sb + (uint32_t)(t % NSTAGE) * STAGE_HB * 2;
        load_tile(s,               pah + (long)m0*lda + ka,    lda, tid);
        load_tile(s + TILE_HB*2,   pal + (long)m0*lda + ka,    lda, tid);
        load_tile(s + 2*TILE_HB*2, Bh  + (long)n0*ldb + kbase, ldb, tid);
        load_tile(s + 3*TILE_HB*2, Bl  + (long)n0*ldb + kbase, ldb, tid);
    };

    load_stage(0); cpa_commit();
    load_stage(1); cpa_commit();
    load_stage(2); cpa_commit();

    const int ar = lane & 15, acg = lane >> 4;
    const int bg = lane >> 3, bl8 = lane & 7;

    for (int t = 0; t < KT; t++) {
        cpa_wait2();          // stage t complete (<=2 newer groups pending)
        __syncthreads();      // publish stage t; all warps done with stage t-1
        if (t + 3 < KT) load_stage(t + 3);   // overwrites buffer (t-1)%4: safe
        cpa_commit();         // keep group accounting uniform

        const uint32_t s = sb + (uint32_t)(t % NSTAGE) * STAGE_HB * 2;
        const uint32_t sAh = s, sAl = s + TILE_HB*2;
        const uint32_t sBh = s + 2*TILE_HB*2, sBl = sBh + TILE_HB*2;

        #pragma unroll
        for (int ks = 0; ks < 2; ks++) {
            uint32_t bh[2][4], bl[2][4];
            #pragma unroll
            for (int nb2 = 0; nb2 < 2; nb2++) {
                int rowb = wcol + nb2*16 + ((bg >> 1) & 1)*8 + bl8;
                int kcb  = ks*16 + (bg & 1)*8;
                uint32_t off = (uint32_t)(rowb*RS + kcb)*2;
                ldm_x4(bh[nb2], sBh + off);
                ldm_x4(bl[nb2], sBl + off);
            }
            #pragma unroll
            for (int mb = 0; mb < 4; mb++) {
                uint32_t ah[4], al[4];
                uint32_t off = (uint32_t)((wrow + mb*16 + ar)*RS + ks*16 + acg*8)*2;
                ldm_x4(ah, sAh + off);
                ldm_x4(al, sAl + off);
                #pragma unroll
                for (int nb = 0; nb < 4; nb++) {
                    const uint32_t* ph = &bh[nb >> 1][(nb & 1)*2];
                    const uint32_t* pl = &bl[nb >> 1][(nb & 1)*2];
                    mma_bf16(acc[mb][nb], ah, ph);
                    mma_bf16(acc[mb][nb], ah, pl);
                    mma_bf16(acc[mb][nb], al, ph);
                }
            }
        }
    }

    // ---- epilogue ----
    const int r0 = lane >> 2, c0 = (lane & 3)*2;
    #pragma unroll
    for (int mb = 0; mb < 4; mb++) {
        #pragma unroll
        for (int nb = 0; nb < 4; nb++) {
            long row = m0 + wrow + mb*16 + r0;
            int  col = n0 + wcol + nb*8 + c0;
            float* a = acc[mb][nb];
            if (C) {
                *(float2*)&C[row*ldc + col]     = make_float2(a[0], a[1]);
                *(float2*)&C[(row+8)*ldc + col] = make_float2(a[2], a[3]);
            }
            if (Coh) {
                uint32_t hi, lo;
                split2(a[0], a[1], hi, lo);
                *(uint32_t*)&Coh[row*ldco + col] = hi;
                *(uint32_t*)&Col[row*ldco + col] = lo;
                split2(a[2], a[3], hi, lo);
                *(uint32_t*)&Coh[(row+8)*ldco + col] = hi;
                *(uint32_t*)&Col[(row+8)*ldco + col] = lo;
            }
        }
    }
}

// ---------------- fused one-time converter ----------------
__global__ void cvt_all(const float* __restrict__ in_m, const float* __restrict__ out_m,
                        const float* __restrict__ w3w, const float* __restrict__ w4w,
                        const float* __restrict__ w5w, const float* __restrict__ w3u,
                        const float* __restrict__ w5u)
{
    long p = ((long)blockIdx.x*blockDim.x + threadIdx.x) * 2;
    const long S0 = 1048576, S1 = 2097152, S2 = S1 + 524288, S3 = S2 + 524288,
               S4 = S3 + 524288, S5 = S4 + 262144, S6 = S5 + 262144;
    if (p >= S6) return;
    const float* src; __nv_bfloat16 *dh, *dl; long off;
    if      (p < S0) { src = in_m;  dh = g_inM_h;  dl = g_inM_l;  off = p; }
    else if (p < S1) { src = out_m; dh = g_outM_h; dl = g_outM_l; off = p - S0; }
    else if (p < S2) { src = w3w; dh = g_wcat_h;           dl = g_wcat_l;           off = p - S1; }
    else if (p < S3) { src = w4w; dh = g_wcat_h + 524288;  dl = g_wcat_l + 524288;  off = p - S2; }
    else if (p < S4) { src = w5w; dh = g_wcat_h + 1048576; dl = g_wcat_l + 1048576; off = p - S3; }
    else if (p < S5) { src = w3u; dh = g_w3u_h; dl = g_w3u_l; off = p - S4; }
    else             { src = w5u; dh = g_w5u_h; dl = g_w5u_l; off = p - S5; }
    float2 v = *(const float2*)&src[off];
    uint32_t h, l;
    split2(v.x, v.y, h, l);
    *(uint32_t*)&dh[off] = h;
    *(uint32_t*)&dl[off] = l;
}

// nodes [b][n][d] fp32 -> ndb hi/lo (straight) + ndT hi/lo (transposed [b][d][n])
__global__ void transpose_cvt(const float* __restrict__ src)
{
    __shared__ float tile[32][33];
    const int b = blockIdx.z;
    const int d0 = blockIdx.x*32, n0 = blockIdx.y*32;
    const float* s = src + (long)b*NN*DD;
    const int tid = threadIdx.x;
    #pragma unroll
    for (int i = 0; i < 4; i++) {
        int p = tid + i*256, n = p >> 5, d = p & 31;
        tile[n][d] = s[(long)(n0+n)*DD + d0 + d];
    }
    __syncthreads();
    #pragma unroll
    for (int i = 0; i < 2; i++) {
        int p = tid + i*256, n = p >> 4, dp = p & 15;
        uint32_t h, l;
        split2(tile[n][dp*2], tile[n][dp*2+1], h, l);
        long o = ((long)b*NN + n0 + n)*DD + d0 + dp*2;
        *(uint32_t*)&g_ndb_h[o] = h; *(uint32_t*)&g_ndb_l[o] = l;
    }
    #pragma unroll
    for (int i = 0; i < 2; i++) {
        int p = tid + i*256, d = p >> 4, np = p & 15;
        uint32_t h, l;
        split2(tile[np*2][d], tile[np*2+1][d], h, l);
        long o = ((long)b*DD + d0 + d)*NN + n0 + np*2;
        *(uint32_t*)&g_ndT_h[o] = h; *(uint32_t*)&g_ndT_l[o] = l;
    }
}

// ---------------- elementwise ----------------
__global__ void elem1(const float* __restrict__ b3w, const float* __restrict__ b3u,
                      const float* __restrict__ b4w)
{
    int p = blockIdx.x*blockDim.x + threadIdx.x;
    long i = (long)p*2;
    int row = (int)(i >> 9), e = (int)(i & 511);
    float2 u = *(const float2*)&g_u3[i];
    float2 f = *(const float2*)&g_nodes[i];
    float g3a = g_gates[(long)row*1536 + e],       g3b = g_gates[(long)row*1536 + e + 1];
    float g4a = g_gates[(long)row*1536 + 512 + e], g4b = g_gates[(long)row*1536 + 512 + e + 1];
    float ua = u.x + b3u[e], ub = u.y + b3u[e+1];
    float za = 1.f/(1.f + expf(-(g3a + b3w[e] + ua)));
    float zb = 1.f/(1.f + expf(-(g3b + b3w[e+1] + ub)));
    float ra = 1.f/(1.f + expf(-(g4a + b4w[e] + ua)));
    float rb = 1.f/(1.f + expf(-(g4b + b4w[e+1] + ub)));
    *(float2*)&g_u3[i] = make_float2(za, zb);
    uint32_t h, l;
    split2(ra*f.x, rb*f.y, h, l);
    *(uint32_t*)&g_rf_h[i] = h;
    *(uint32_t*)&g_rf_l[i] = l;
}

__global__ void elem2(const float* __restrict__ b5w, const float* __restrict__ b5u)
{
    long i = (long)blockIdx.x*blockDim.x + threadIdx.x;
    int row = (int)(i >> 9), e = (int)(i & 511);
    float t  = g_t[i];
    float g5 = g_gates[(long)row*1536 + 1024 + e];
    float hv = tanhf(g5 + b5w[e] + t + b5u[e]);
    float z  = g_u3[i];
    float f  = g_nodes[i];
    g_nodes[i] = (1.f - z)*f + z*hv;
}

__global__ void copy4(const float4* __restrict__ src, float4* __restrict__ dst, int n4)
{
    int i = blockIdx.x*blockDim.x + threadIdx.x;
    if (i < n4) dst[i] = src[i];
}

// ---------------- host launcher ----------------
extern "C" void kernel_launch(void* const* d_in, const int* in_sizes, int n_in,
                              void* d_out, int out_size)
{
    (void)in_sizes; (void)n_in; (void)out_size;
    const float* x     = (const float*)d_in[0];
    const float* in_m  = (const float*)d_in[1];
    const float* out_m = (const float*)d_in[2];
    const float* w3w   = (const float*)d_in[3];
    const float* b3w   = (const float*)d_in[4];
    const float* w3u   = (const float*)d_in[5];
    const float* b3u   = (const float*)d_in[6];
    const float* w4w   = (const float*)d_in[7];
    const float* b4w   = (const float*)d_in[8];
    const float* w5w   = (const float*)d_in[9];
    const float* b5w   = (const float*)d_in[10];
    const float* w5u   = (const float*)d_in[11];
    const float* b5u   = (const float*)d_in[12];
    float* out = (float*)d_out;

    float *nodes, *u3, *tt, *gates;
    cudaGetSymbolAddress((void**)&nodes, g_nodes);
    cudaGetSymbolAddress((void**)&u3,    g_u3);
    cudaGetSymbolAddress((void**)&tt,    g_t);
    cudaGetSymbolAddress((void**)&gates, g_gates);

    __nv_bfloat16 *inMh,*inMl,*outMh,*outMl,*wcath,*wcatl;
    __nv_bfloat16 *w3uh,*w3ul,*w5uh,*w5ul,*ndTh,*ndTl,*ndbh,*ndbl;
    __nv_bfloat16 *ainh,*ainl,*aouth,*aoutl,*rfh,*rfl;
    cudaGetSymbolAddress((void**)&inMh, g_inM_h);  cudaGetSymbolAddress((void**)&inMl, g_inM_l);
    cudaGetSymbolAddress((void**)&outMh,g_outM_h); cudaGetSymbolAddress((void**)&outMl,g_outM_l);
    cudaGetSymbolAddress((void**)&wcath,g_wcat_h); cudaGetSymbolAddress((void**)&wcatl,g_wcat_l);
    cudaGetSymbolAddress((void**)&w3uh, g_w3u_h);  cudaGetSymbolAddress((void**)&w3ul, g_w3u_l);
    cudaGetSymbolAddress((void**)&w5uh, g_w5u_h);  cudaGetSymbolAddress((void**)&w5ul, g_w5u_l);
    cudaGetSymbolAddress((void**)&ndTh, g_ndT_h);  cudaGetSymbolAddress((void**)&ndTl, g_ndT_l);
    cudaGetSymbolAddress((void**)&ndbh, g_ndb_h);  cudaGetSymbolAddress((void**)&ndbl, g_ndb_l);
    cudaGetSymbolAddress((void**)&ainh, g_ain_h);  cudaGetSymbolAddress((void**)&ainl, g_ain_l);
    cudaGetSymbolAddress((void**)&aouth,g_aout_h); cudaGetSymbolAddress((void**)&aoutl,g_aout_l);
    cudaGetSymbolAddress((void**)&rfh,  g_rf_h);   cudaGetSymbolAddress((void**)&rfl,  g_rf_l);

    cudaFuncSetAttribute(gemm_mma, cudaFuncAttributeMaxDynamicSharedMemorySize, GEMM_SMEM);

    const long ND = (long)NN*DD;     // 524288
    const int  BIG = 1 << 30;

    copy4<<<(BB*NN*DD/4 + 255)/256, 256>>>((const float4*)x, (float4*)nodes, BB*NN*DD/4);
    cvt_all<<<8192, 256>>>(in_m, out_m, w3w, w4w, w5w, w3u, w5u);

    for (int step = 0; step < TIME_STEP; step++) {
        transpose_cvt<<<dim3(DD/32, NN/32, BB), 256>>>(nodes);

        // fused a_in + a_out: M=1024, N=512, K=1024, z=0..31 (z>=16 -> out_matrix)
        dim3 gp(DD/128, NN/128, 2*BB);
        gemm_mma<<<gp, NT, GEMM_SMEM>>>(inMh, inMl, outMh, outMl, BIG, NN, 1,
                                        ndTh, ndTl, NN,
                                        nullptr, 0,
                                        ainh, ainl, aouth, aoutl, DD,
                                        NN, 0L, ND, 0L, ND);

        // fused gates: [ain|aout] @ wcat^T, M=16384, N=1536, K=1024 (split at 512)
        dim3 gg3(3*DD/128, ROWS/128, 1);   // (12, 128)
        gemm_mma<<<gg3, NT, GEMM_SMEM>>>(ainh, ainl, aouth, aoutl, DD, DD, 0,
                                         wcath, wcatl, 2*DD,
                                         gates, 3*DD,
                                         nullptr, nullptr, nullptr, nullptr, 0,
                                         2*DD, 0L, 0L, 0L, 0L);

        // u3 = nodes @ w3u^T, M=16384, N=512, K=512
        dim3 gg(DD/128, ROWS/128, 1);
        gemm_mma<<<gg, NT, GEMM_SMEM>>>(ndbh, ndbl, ndbh, ndbl, BIG, DD, 0,
                                        w3uh, w3ul, DD,
                                        u3, DD,
                                        nullptr, nullptr, nullptr, nullptr, 0,
                                        DD, 0L, 0L, 0L, 0L);

        elem1<<<ROWS*DD/2/256, 256>>>(b3w, b3u, b4w);

        // t = (rv*f) @ w5u^T
        gemm_mma<<<gg, NT, GEMM_SMEM>>>(rfh, rfl, rfh, rfl, BIG, DD, 0,
                                        w5uh, w5ul, DD,
                                        tt, DD,
                                        nullptr, nullptr, nullptr, nullptr, 0,
                                        DD, 0L, 0L, 0L, 0L);

        elem2<<<ROWS*DD/256, 256>>>(b5w, b5u);
    }

    copy4<<<(BB*NN*DD/4 + 255)/256, 256>>>((const float4*)nodes, (float4*)out, BB*NN*DD/4);
    copy4<<<(NN*NN/4 + 255)/256, 256>>>((const float4*)in_m,
                                        (float4*)(out + (long)BB*NN*DD), NN*NN/4);
}

// round 12
// speedup vs baseline: 1.5203x; 1.0085x over previous
#include <cuda_runtime.h>
#include <cuda_bf16.h>
#include <cstdint>
#include <math.h>

#define BB 16
#define NN 1024
#define DD 512
#define ROWS (BB*NN)          // 16384
#define TIME_STEP 3

// ---------------- fp32 scratch ----------------
__device__ float g_nodes[BB*NN*DD];
__device__ float g_u3   [BB*NN*DD];          // u3, then zv
__device__ float g_t    [BB*NN*DD];          // (rv*f)@w5u^T
__device__ float g_gates[BB*NN*3*DD];        // [16384][1536]

// ---------------- bf16 hi/lo operand buffers ----------------
__device__ __nv_bfloat16 g_inM_h [NN*NN], g_inM_l [NN*NN];
__device__ __nv_bfloat16 g_outM_h[NN*NN], g_outM_l[NN*NN];
__device__ __nv_bfloat16 g_wcat_h[3*DD*2*DD], g_wcat_l[3*DD*2*DD];  // [1536][1024]
__device__ __nv_bfloat16 g_w3u_h[DD*DD],   g_w3u_l[DD*DD];
__device__ __nv_bfloat16 g_w5u_h[DD*DD],   g_w5u_l[DD*DD];
__device__ __nv_bfloat16 g_ndT_h[BB*DD*NN], g_ndT_l[BB*DD*NN];   // [b][d][n]
__device__ __nv_bfloat16 g_ndb_h[BB*NN*DD], g_ndb_l[BB*NN*DD];   // [b][n][d]
__device__ __nv_bfloat16 g_ain_h[BB*NN*DD], g_ain_l[BB*NN*DD];
__device__ __nv_bfloat16 g_aout_h[BB*NN*DD], g_aout_l[BB*NN*DD];
__device__ __nv_bfloat16 g_rf_h [BB*NN*DD], g_rf_l [BB*NN*DD];

// ---------------- helpers ----------------
__device__ __forceinline__ uint32_t smem_u32(const void* p) {
    uint32_t a;
    asm("{ .reg .u64 t; cvta.to.shared.u64 t, %1; cvt.u32.u64 %0, t; }" : "=r"(a) : "l"(p));
    return a;
}
__device__ __forceinline__ void split2(float x, float y, uint32_t& hi, uint32_t& lo) {
    __nv_bfloat162 h = __floats2bfloat162_rn(x, y);   // low=x, high=y
    float rx = x - __bfloat162float(__low2bfloat16(h));
    float ry = y - __bfloat162float(__high2bfloat16(h));
    __nv_bfloat162 l = __floats2bfloat162_rn(rx, ry);
    hi = *(uint32_t*)&h; lo = *(uint32_t*)&l;
}
__device__ __forceinline__ void cpa16(uint32_t s, const void* g) {
    asm volatile("cp.async.cg.shared.global [%0], [%1], 16;" :: "r"(s), "l"(g));
}
__device__ __forceinline__ void cpa_commit() {
    asm volatile("cp.async.commit_group;" ::: "memory");
}
__device__ __forceinline__ void cpa_wait2() {
    asm volatile("cp.async.wait_group 2;" ::: "memory");
}
__device__ __forceinline__ void ldm_x4(uint32_t* r, uint32_t addr) {
    asm volatile("ldmatrix.sync.aligned.m8n8.x4.shared.b16 {%0,%1,%2,%3}, [%4];"
                 : "=r"(r[0]), "=r"(r[1]), "=r"(r[2]), "=r"(r[3]) : "r"(addr));
}
__device__ __forceinline__ void mma_bf16(float* d, const uint32_t* a, const uint32_t* b) {
    asm volatile("mma.sync.aligned.m16n8k16.row.col.f32.bf16.bf16.f32 "
                 "{%0,%1,%2,%3}, {%4,%5,%6,%7}, {%8,%9}, {%0,%1,%2,%3};"
                 : "+f"(d[0]), "+f"(d[1]), "+f"(d[2]), "+f"(d[3])
                 : "r"(a[0]), "r"(a[1]), "r"(a[2]), "r"(a[3]), "r"(b[0]), "r"(b[1]));
}

// ======================= bf16x3 mma.sync GEMM (128x128 CTA, 256 thr) ==========
// Warp grid 2 rows x 4 cols, warp tile 64x32. Term-major MMA issue order:
// all hi*hi, then all hi*lo, then all lo*hi -> same-acc reuse distance 16.
// C[m][n] = sum_k A'[m][k]*B[n][k]; A,B pre-split bf16 hi/lo, k-major.
// msel=0: A' = A for k<ksplit else A2 at k-ksplit; batch z via aB/bB/cB/coB.
// msel=1: matrix pair (A vs A2) chosen by z>=16; batch = z&15; epilogue goes
//         to (Coh,Col) for z<16 and (Co2h,Co2l) for z>=16. ksplit unused.
#define KC 32
#define RS 40                      // smem row stride in halves (80B, 16B-aligned)
#define TILE_HB (128*RS)           // halves per tile
#define STAGE_HB (4*TILE_HB)       // Ahi|Alo|Bhi|Blo
#define NSTAGE 4
#define GEMM_SMEM (NSTAGE*STAGE_HB*2)   // 163840 bytes
#define NT 256

__device__ __forceinline__ void load_tile(uint32_t sbase, const __nv_bfloat16* g,
                                          int ld, int tid)
{
    int row = tid >> 2, cb = tid & 3;      // 256 threads: 2x 16B per tile
    cpa16(sbase + (uint32_t)(row*RS + cb*8)*2, g + (long)row*ld + cb*8);
    cpa16(sbase + (uint32_t)((row+64)*RS + cb*8)*2, g + (long)(row+64)*ld + cb*8);
}

__global__ __launch_bounds__(NT, 1)
void gemm_mma(const __nv_bfloat16* __restrict__ Ah, const __nv_bfloat16* __restrict__ Al,
              const __nv_bfloat16* __restrict__ A2h, const __nv_bfloat16* __restrict__ A2l,
              int ksplit, int lda, int msel,
              const __nv_bfloat16* __restrict__ Bh, const __nv_bfloat16* __restrict__ Bl,
              int ldb,
              float* __restrict__ C, int ldc,
              __nv_bfloat16* __restrict__ Coh, __nv_bfloat16* __restrict__ Col,
              __nv_bfloat16* __restrict__ Co2h, __nv_bfloat16* __restrict__ Co2l,
              int ldco,
              int Kd, long aB, long bB, long cB, long coB)
{
    extern __shared__ char smem[];
    const uint32_t sb = smem_u32(smem);

    long z = blockIdx.z;
    if (msel) {
        if (z >= 16) { Ah = A2h; Al = A2l; Coh = Co2h; Col = Co2l; z -= 16; }
        A2h = Ah; A2l = Al;
        ksplit = 1 << 30;
    }
    Ah += z*aB; Al += z*aB; A2h += z*aB; A2l += z*aB;
    Bh += z*bB; Bl += z*bB;
    if (C)   C   += z*cB;
    if (Coh) { Coh += z*coB; Col += z*coB; }

    const int tid = threadIdx.x;
    const int wid = tid >> 5, lane = tid & 31;
    const int m0 = blockIdx.y * 128, n0 = blockIdx.x * 128;
    const int wrow = (wid & 1) * 64;       // 2 warp-rows x 64
    const int wcol = (wid >> 1) * 32;      // 4 warp-cols x 32

    float acc[4][4][4];                    // [mb][nb][frag] : 64x32 warp tile
    #pragma unroll
    for (int i = 0; i < 4; i++)
        #pragma unroll
        for (int j = 0; j < 4; j++)
            #pragma unroll
            for (int k = 0; k < 4; k++) acc[i][j][k] = 0.f;

    const int KT = Kd / KC;

    auto load_stage = [&](int t) {
        int kbase = t * KC;
        const __nv_bfloat16 *pah = Ah, *pal = Al;
        int ka = kbase;
        if (kbase >= ksplit) { pah = A2h; pal = A2l; ka -= ksplit; }
        uint32_t s = sb + (uint32_t)(t % NSTAGE) * STAGE_HB * 2;
        load_tile(s,               pah + (long)m0*lda + ka,    lda, tid);
        load_tile(s + TILE_HB*2,   pal + (long)m0*lda + ka,    lda, tid);
        load_tile(s + 2*TILE_HB*2, Bh  + (long)n0*ldb + kbase, ldb, tid);
        load_tile(s + 3*TILE_HB*2, Bl  + (long)n0*ldb + kbase, ldb, tid);
    };

    load_stage(0); cpa_commit();
    load_stage(1); cpa_commit();
    load_stage(2); cpa_commit();

    const int ar = lane & 15, acg = lane >> 4;
    const int bg = lane >> 3, bl8 = lane & 7;

    for (int t = 0; t < KT; t++) {
        cpa_wait2();          // stage t complete (<=2 newer groups pending)
        __syncthreads();      // publish stage t; all warps done with stage t-1
        if (t + 3 < KT) load_stage(t + 3);   // overwrites buffer (t-1)%4: safe
        cpa_commit();         // keep group accounting uniform

        const uint32_t s = sb + (uint32_t)(t % NSTAGE) * STAGE_HB * 2;
        const uint32_t sAh = s, sAl = s + TILE_HB*2;
        const uint32_t sBh = s + 2*TILE_HB*2, sBl = sBh + TILE_HB*2;

        #pragma unroll
        for (int ks = 0; ks < 2; ks++) {
            uint32_t bh[2][4], bl[2][4];
            #pragma unroll
            for (int nb2 = 0; nb2 < 2; nb2++) {
                int rowb = wcol + nb2*16 + ((bg >> 1) & 1)*8 + bl8;
                int kcb  = ks*16 + (bg & 1)*8;
                uint32_t off = (uint32_t)(rowb*RS + kcb)*2;
                ldm_x4(bh[nb2], sBh + off);
                ldm_x4(bl[nb2], sBl + off);
            }
            uint32_t ah[4][4], al[4][4];
            #pragma unroll
            for (int mb = 0; mb < 4; mb++) {
                uint32_t off = (uint32_t)((wrow + mb*16 + ar)*RS + ks*16 + acg*8)*2;
                ldm_x4(ah[mb], sAh + off);
                ldm_x4(al[mb], sAl + off);
            }
            // term-major issue: all hi*hi, then hi*lo, then lo*hi
            #pragma unroll
            for (int mb = 0; mb < 4; mb++)
                #pragma unroll
                for (int nb = 0; nb < 4; nb++)
                    mma_bf16(acc[mb][nb], ah[mb], &bh[nb >> 1][(nb & 1)*2]);
            #pragma unroll
            for (int mb = 0; mb < 4; mb++)
                #pragma unroll
                for (int nb = 0; nb < 4; nb++)
                    mma_bf16(acc[mb][nb], ah[mb], &bl[nb >> 1][(nb & 1)*2]);
            #pragma unroll
            for (int mb = 0; mb < 4; mb++)
                #pragma unroll
                for (int nb = 0; nb < 4; nb++)
                    mma_bf16(acc[mb][nb], al[mb], &bh[nb >> 1][(nb & 1)*2]);
        }
    }

    // ---- epilogue ----
    const int r0 = lane >> 2, c0 = (lane & 3)*2;
    #pragma unroll
    for (int mb = 0; mb < 4; mb++) {
        #pragma unroll
        for (int nb = 0; nb < 4; nb++) {
            long row = m0 + wrow + mb*16 + r0;
            int  col = n0 + wcol + nb*8 + c0;
            float* a = acc[mb][nb];
            if (C) {
                *(float2*)&C[row*ldc + col]     = make_float2(a[0], a[1]);
                *(float2*)&C[(row+8)*ldc + col] = make_float2(a[2], a[3]);
            }
            if (Coh) {
                uint32_t hi, lo;
                split2(a[0], a[1], hi, lo);
                *(uint32_t*)&Coh[row*ldco + col] = hi;
                *(uint32_t*)&Col[row*ldco + col] = lo;
                split2(a[2], a[3], hi, lo);
                *(uint32_t*)&Coh[(row+8)*ldco + col] = hi;
                *(uint32_t*)&Col[(row+8)*ldco + col] = lo;
            }
        }
    }
}

// ---------------- fused one-time converter ----------------
__global__ void cvt_all(const float* __restrict__ in_m, const float* __restrict__ out_m,
                        const float* __restrict__ w3w, const float* __restrict__ w4w,
                        const float* __restrict__ w5w, const float* __restrict__ w3u,
                        const float* __restrict__ w5u)
{
    long p = ((long)blockIdx.x*blockDim.x + threadIdx.x) * 2;
    const long S0 = 1048576, S1 = 2097152, S2 = S1 + 524288, S3 = S2 + 524288,
               S4 = S3 + 524288, S5 = S4 + 262144, S6 = S5 + 262144;
    if (p >= S6) return;
    const float* src; __nv_bfloat16 *dh, *dl; long off;
    if      (p < S0) { src = in_m;  dh = g_inM_h;  dl = g_inM_l;  off = p; }
    else if (p < S1) { src = out_m; dh = g_outM_h; dl = g_outM_l; off = p - S0; }
    else if (p < S2) { src = w3w; dh = g_wcat_h;           dl = g_wcat_l;           off = p - S1; }
    else if (p < S3) { src = w4w; dh = g_wcat_h + 524288;  dl = g_wcat_l + 524288;  off = p - S2; }
    else if (p < S4) { src = w5w; dh = g_wcat_h + 1048576; dl = g_wcat_l + 1048576; off = p - S3; }
    else if (p < S5) { src = w3u; dh = g_w3u_h; dl = g_w3u_l; off = p - S4; }
    else             { src = w5u; dh = g_w5u_h; dl = g_w5u_l; off = p - S5; }
    float2 v = *(const float2*)&src[off];
    uint32_t h, l;
    split2(v.x, v.y, h, l);
    *(uint32_t*)&dh[off] = h;
    *(uint32_t*)&dl[off] = l;
}

// nodes [b][n][d] fp32 -> ndb hi/lo (straight) + ndT hi/lo (transposed [b][d][n])
__global__ void transpose_cvt(const float* __restrict__ src)
{
    __shared__ float tile[32][33];
    const int b = blockIdx.z;
    const int d0 = blockIdx.x*32, n0 = blockIdx.y*32;
    const float* s = src + (long)b*NN*DD;
    const int tid = threadIdx.x;
    #pragma unroll
    for (int i = 0; i < 4; i++) {
        int p = tid + i*256, n = p >> 5, d = p & 31;
        tile[n][d] = s[(long)(n0+n)*DD + d0 + d];
    }
    __syncthreads();
    #pragma unroll
    for (int i = 0; i < 2; i++) {
        int p = tid + i*256, n = p >> 4, dp = p & 15;
        uint32_t h, l;
        split2(tile[n][dp*2], tile[n][dp*2+1], h, l);
        long o = ((long)b*NN + n0 + n)*DD + d0 + dp*2;
        *(uint32_t*)&g_ndb_h[o] = h; *(uint32_t*)&g_ndb_l[o] = l;
    }
    #pragma unroll
    for (int i = 0; i < 2; i++) {
        int p = tid + i*256, d = p >> 4, np = p & 15;
        uint32_t h, l;
        split2(tile[np*2][d], tile[np*2+1][d], h, l);
        long o = ((long)b*DD + d0 + d)*NN + n0 + np*2;
        *(uint32_t*)&g_ndT_h[o] = h; *(uint32_t*)&g_ndT_l[o] = l;
    }
}

// ---------------- elementwise ----------------
__global__ void elem1(const float* __restrict__ b3w, const float* __restrict__ b3u,
                      const float* __restrict__ b4w)
{
    int p = blockIdx.x*blockDim.x + threadIdx.x;
    long i = (long)p*2;
    int row = (int)(i >> 9), e = (int)(i & 511);
    float2 u = *(const float2*)&g_u3[i];
    float2 f = *(const float2*)&g_nodes[i];
    float g3a = g_gates[(long)row*1536 + e],       g3b = g_gates[(long)row*1536 + e + 1];
    float g4a = g_gates[(long)row*1536 + 512 + e], g4b = g_gates[(long)row*1536 + 512 + e + 1];
    float ua = u.x + b3u[e], ub = u.y + b3u[e+1];
    float za = 1.f/(1.f + expf(-(g3a + b3w[e] + ua)));
    float zb = 1.f/(1.f + expf(-(g3b + b3w[e+1] + ub)));
    float ra = 1.f/(1.f + expf(-(g4a + b4w[e] + ua)));
    float rb = 1.f/(1.f + expf(-(g4b + b4w[e+1] + ub)));
    *(float2*)&g_u3[i] = make_float2(za, zb);
    uint32_t h, l;
    split2(ra*f.x, rb*f.y, h, l);
    *(uint32_t*)&g_rf_h[i] = h;
    *(uint32_t*)&g_rf_l[i] = l;
}

__global__ void elem2(const float* __restrict__ b5w, const float* __restrict__ b5u)
{
    long i = (long)blockIdx.x*blockDim.x + threadIdx.x;
    int row = (int)(i >> 9), e = (int)(i & 511);
    float t  = g_t[i];
    float g5 = g_gates[(long)row*1536 + 1024 + e];
    float hv = tanhf(g5 + b5w[e] + t + b5u[e]);
    float z  = g_u3[i];
    float f  = g_nodes[i];
    g_nodes[i] = (1.f - z)*f + z*hv;
}

__global__ void copy4(const float4* __restrict__ src, float4* __restrict__ dst, int n4)
{
    int i = blockIdx.x*blockDim.x + threadIdx.x;
    if (i < n4) dst[i] = src[i];
}

// ---------------- host launcher ----------------
extern "C" void kernel_launch(void* const* d_in, const int* in_sizes, int n_in,
                              void* d_out, int out_size)
{
    (void)in_sizes; (void)n_in; (void)out_size;
    const float* x     = (const float*)d_in[0];
    const float* in_m  = (const float*)d_in[1];
    const float* out_m = (const float*)d_in[2];
    const float* w3w   = (const float*)d_in[3];
    const float* b3w   = (const float*)d_in[4];
    const float* w3u   = (const float*)d_in[5];
    const float* b3u   = (const float*)d_in[6];
    const float* w4w   = (const float*)d_in[7];
    const float* b4w   = (const float*)d_in[8];
    const float* w5w   = (const float*)d_in[9];
    const float* b5w   = (const float*)d_in[10];
    const float* w5u   = (const float*)d_in[11];
    const float* b5u   = (const float*)d_in[12];
    float* out = (float*)d_out;

    float *nodes, *u3, *tt, *gates;
    cudaGetSymbolAddress((void**)&nodes, g_nodes);
    cudaGetSymbolAddress((void**)&u3,    g_u3);
    cudaGetSymbolAddress((void**)&tt,    g_t);
    cudaGetSymbolAddress((void**)&gates, g_gates);

    __nv_bfloat16 *inMh,*inMl,*outMh,*outMl,*wcath,*wcatl;
    __nv_bfloat16 *w3uh,*w3ul,*w5uh,*w5ul,*ndTh,*ndTl,*ndbh,*ndbl;
    __nv_bfloat16 *ainh,*ainl,*aouth,*aoutl,*rfh,*rfl;
    cudaGetSymbolAddress((void**)&inMh, g_inM_h);  cudaGetSymbolAddress((void**)&inMl, g_inM_l);
    cudaGetSymbolAddress((void**)&outMh,g_outM_h); cudaGetSymbolAddress((void**)&outMl,g_outM_l);
    cudaGetSymbolAddress((void**)&wcath,g_wcat_h); cudaGetSymbolAddress((void**)&wcatl,g_wcat_l);
    cudaGetSymbolAddress((void**)&w3uh, g_w3u_h);  cudaGetSymbolAddress((void**)&w3ul, g_w3u_l);
    cudaGetSymbolAddress((void**)&w5uh, g_w5u_h);  cudaGetSymbolAddress((void**)&w5ul, g_w5u_l);
    cudaGetSymbolAddress((void**)&ndTh, g_ndT_h);  cudaGetSymbolAddress((void**)&ndTl, g_ndT_l);
    cudaGetSymbolAddress((void**)&ndbh, g_ndb_h);  cudaGetSymbolAddress((void**)&ndbl, g_ndb_l);
    cudaGetSymbolAddress((void**)&ainh, g_ain_h);  cudaGetSymbolAddress((void**)&ainl, g_ain_l);
    cudaGetSymbolAddress((void**)&aouth,g_aout_h); cudaGetSymbolAddress((void**)&aoutl,g_aout_l);
    cudaGetSymbolAddress((void**)&rfh,  g_rf_h);   cudaGetSymbolAddress((void**)&rfl,  g_rf_l);

    cudaFuncSetAttribute(gemm_mma, cudaFuncAttributeMaxDynamicSharedMemorySize, GEMM_SMEM);

    const long ND = (long)NN*DD;     // 524288
    const int  BIG = 1 << 30;

    copy4<<<(BB*NN*DD/4 + 255)/256, 256>>>((const float4*)x, (float4*)nodes, BB*NN*DD/4);
    cvt_all<<<8192, 256>>>(in_m, out_m, w3w, w4w, w5w, w3u, w5u);

    for (int step = 0; step < TIME_STEP; step++) {
        transpose_cvt<<<dim3(DD/32, NN/32, BB), 256>>>(nodes);

        // fused a_in + a_out: M=1024, N=512, K=1024, z=0..31 (z>=16 -> out_matrix)
        dim3 gp(DD/128, NN/128, 2*BB);
        gemm_mma<<<gp, NT, GEMM_SMEM>>>(inMh, inMl, outMh, outMl, BIG, NN, 1,
                                        ndTh, ndTl, NN,
                                        nullptr, 0,
                                        ainh, ainl, aouth, aoutl, DD,
                                        NN, 0L, ND, 0L, ND);

        // fused gates: [ain|aout] @ wcat^T, M=16384, N=1536, K=1024 (split at 512)
        dim3 gg3(3*DD/128, ROWS/128, 1);   // (12, 128)
        gemm_mma<<<gg3, NT, GEMM_SMEM>>>(ainh, ainl, aouth, aoutl, DD, DD, 0,
                                         wcath, wcatl, 2*DD,
                                         gates, 3*DD,
                                         nullptr, nullptr, nullptr, nullptr, 0,
                                         2*DD, 0L, 0L, 0L, 0L);

        // u3 = nodes @ w3u^T, M=16384, N=512, K=512
        dim3 gg(DD/128, ROWS/128, 1);
        gemm_mma<<<gg, NT, GEMM_SMEM>>>(ndbh, ndbl, ndbh, ndbl, BIG, DD, 0,
                                        w3uh, w3ul, DD,
                                        u3, DD,
                                        nullptr, nullptr, nullptr, nullptr, 0,
                                        DD, 0L, 0L, 0L, 0L);

        elem1<<<ROWS*DD/2/256, 256>>>(b3w, b3u, b4w);

        // t = (rv*f) @ w5u^T
        gemm_mma<<<gg, NT, GEMM_SMEM>>>(rfh, rfl, rfh, rfl, BIG, DD, 0,
                                        w5uh, w5ul, DD,
                                        tt, DD,
                                        nullptr, nullptr, nullptr, nullptr, 0,
                                        DD, 0L, 0L, 0L, 0L);

        elem2<<<ROWS*DD/256, 256>>>(b5w, b5u);
    }

    copy4<<<(BB*NN*DD/4 + 255)/256, 256>>>((const float4*)nodes, (float4*)out, BB*NN*DD/4);
    copy4<<<(NN*NN/4 + 255)/256, 256>>>((const float4*)in_m,
                                        (float4*)(out + (long)BB*NN*DD), NN*NN/4);
}

// round 13
// speedup vs baseline: 1.8357x; 1.2075x over previous
#include <cuda_runtime.h>
#include <cuda_fp16.h>
#include <cstdint>
#include <math.h>

#define BB 16
#define NN 1024
#define DD 512
#define ROWS (BB*NN)          // 16384
#define TIME_STEP 3

// ---------------- fp32 scratch ----------------
__device__ float g_nodes[BB*NN*DD];
__device__ float g_u3   [BB*NN*DD];          // u3, then zv
__device__ float g_t    [BB*NN*DD];          // (rv*f)@w5u^T
__device__ float g_gates[BB*NN*3*DD];        // [16384][1536]

// ---------------- fp16 hi/lo operand buffers ----------------
__device__ __half g_inM_h [NN*NN], g_inM_l [NN*NN];
__device__ __half g_outM_h[NN*NN], g_outM_l[NN*NN];
__device__ __half g_wcat_h[3*DD*2*DD];               // [1536][1024] single
__device__ __half g_w3u_h[DD*DD];
__device__ __half g_w5u_h[DD*DD];
__device__ __half g_ndT_h[BB*DD*NN], g_ndT_l[BB*DD*NN];   // [b][d][n]
__device__ __half g_ndb_h[BB*NN*DD], g_ndb_l[BB*NN*DD];   // [b][n][d]
__device__ __half g_ain_h[BB*NN*DD], g_ain_l[BB*NN*DD];
__device__ __half g_aout_h[BB*NN*DD], g_aout_l[BB*NN*DD];
__device__ __half g_rf_h [BB*NN*DD], g_rf_l [BB*NN*DD];

// ---------------- helpers ----------------
__device__ __forceinline__ uint32_t smem_u32(const void* p) {
    uint32_t a;
    asm("{ .reg .u64 t; cvta.to.shared.u64 t, %1; cvt.u32.u64 %0, t; }" : "=r"(a) : "l"(p));
    return a;
}
__device__ __forceinline__ void split2h(float x, float y, uint32_t& hi, uint32_t& lo) {
    __half2 h = __floats2half2_rn(x, y);   // low=x, high=y
    float rx = x - __half2float(__low2half(h));
    float ry = y - __half2float(__high2half(h));
    __half2 l = __floats2half2_rn(rx, ry);
    hi = *(uint32_t*)&h; lo = *(uint32_t*)&l;
}
__device__ __forceinline__ void cpa16(uint32_t s, const void* g) {
    asm volatile("cp.async.cg.shared.global [%0], [%1], 16;" :: "r"(s), "l"(g));
}
__device__ __forceinline__ void cpa_commit() {
    asm volatile("cp.async.commit_group;" ::: "memory");
}
__device__ __forceinline__ void cpa_wait2() {
    asm volatile("cp.async.wait_group 2;" ::: "memory");
}
__device__ __forceinline__ void ldm_x4(uint32_t* r, uint32_t addr) {
    asm volatile("ldmatrix.sync.aligned.m8n8.x4.shared.b16 {%0,%1,%2,%3}, [%4];"
                 : "=r"(r[0]), "=r"(r[1]), "=r"(r[2]), "=r"(r[3]) : "r"(addr));
}
__device__ __forceinline__ void mma_f16(float* d, const uint32_t* a, const uint32_t* b) {
    asm volatile("mma.sync.aligned.m16n8k16.row.col.f32.f16.f16.f32 "
                 "{%0,%1,%2,%3}, {%4,%5,%6,%7}, {%8,%9}, {%0,%1,%2,%3};"
                 : "+f"(d[0]), "+f"(d[1]), "+f"(d[2]), "+f"(d[3])
                 : "r"(a[0]), "r"(a[1]), "r"(a[2]), "r"(a[3]), "r"(b[0]), "r"(b[1]));
}

// ======================= fp16 split mma.sync GEMM =======================
// NTERMS=3: C = Ahi*Bhi + Ahi*Blo + Alo*Bhi    (A and B both hi/lo split)
// NTERMS=2: C = Ahi*B + Alo*B                  (B single fp16; Bl unused)
// 128x128 CTA, 256 threads, warp grid 2x4 (warp tile 64x32).
// msel=0: A' = A for k<ksplit else A2 at k-ksplit; batch z via aB/bB/cB/coB.
// msel=1: matrix pair (A vs A2) chosen by z>=16; batch = z&15; epilogue goes
//         to (Coh,Col) for z<16 and (Co2h,Co2l) for z>=16. ksplit unused.
#define KC 32
#define RS 40                      // smem row stride in halves (80B, 16B-aligned)
#define TILE_HB (128*RS)           // halves per tile (5120)
#define NSTAGE 4
#define NT 256
#define SMEM3 (NSTAGE*4*TILE_HB*2)   // 163840
#define SMEM2 (NSTAGE*3*TILE_HB*2)   // 122880

__device__ __forceinline__ void load_tile(uint32_t sbase, const __half* g,
                                          int ld, int tid)
{
    int row = tid >> 2, cb = tid & 3;      // 256 threads: 2x 16B per tile
    cpa16(sbase + (uint32_t)(row*RS + cb*8)*2, g + (long)row*ld + cb*8);
    cpa16(sbase + (uint32_t)((row+64)*RS + cb*8)*2, g + (long)(row+64)*ld + cb*8);
}

template<int NTERMS>
__global__ __launch_bounds__(NT, 1)
void gemm_mma(const __half* __restrict__ Ah, const __half* __restrict__ Al,
              const __half* __restrict__ A2h, const __half* __restrict__ A2l,
              int ksplit, int lda, int msel,
              const __half* __restrict__ Bh, const __half* __restrict__ Bl,
              int ldb,
              float* __restrict__ C, int ldc,
              __half* __restrict__ Coh, __half* __restrict__ Col,
              __half* __restrict__ Co2h, __half* __restrict__ Co2l,
              int ldco,
              int Kd, long aB, long bB, long cB, long coB)
{
    constexpr int TILES = NTERMS + 1;                 // 4 or 3
    constexpr uint32_t STAGE_B = (uint32_t)TILES * TILE_HB * 2;

    extern __shared__ char smem[];
    const uint32_t sb = smem_u32(smem);

    long z = blockIdx.z;
    if (msel) {
        if (z >= 16) { Ah = A2h; Al = A2l; Coh = Co2h; Col = Co2l; z -= 16; }
        A2h = Ah; A2l = Al;
        ksplit = 1 << 30;
    }
    Ah += z*aB; Al += z*aB; A2h += z*aB; A2l += z*aB;
    Bh += z*bB; if (NTERMS == 3) Bl += z*bB;
    if (C)   C   += z*cB;
    if (Coh) { Coh += z*coB; Col += z*coB; }

    const int tid = threadIdx.x;
    const int wid = tid >> 5, lane = tid & 31;
    const int m0 = blockIdx.y * 128, n0 = blockIdx.x * 128;
    const int wrow = (wid & 1) * 64;       // 2 warp-rows x 64
    const int wcol = (wid >> 1) * 32;      // 4 warp-cols x 32

    float acc[4][4][4];                    // [mb][nb][frag] : 64x32 warp tile
    #pragma unroll
    for (int i = 0; i < 4; i++)
        #pragma unroll
        for (int j = 0; j < 4; j++)
            #pragma unroll
            for (int k = 0; k < 4; k++) acc[i][j][k] = 0.f;

    const int KT = Kd / KC;

    auto load_stage = [&](int t) {
        int kbase = t * KC;
        const __half *pah = Ah, *pal = Al;
        int ka = kbase;
        if (kbase >= ksplit) { pah = A2h; pal = A2l; ka -= ksplit; }
        uint32_t s = sb + (uint32_t)(t % NSTAGE) * STAGE_B;
        load_tile(s,               pah + (long)m0*lda + ka,    lda, tid);
        load_tile(s + TILE_HB*2,   pal + (long)m0*lda + ka,    lda, tid);
        load_tile(s + 2*TILE_HB*2, Bh  + (long)n0*ldb + kbase, ldb, tid);
        if (NTERMS == 3)
            load_tile(s + 3*TILE_HB*2, Bl + (long)n0*ldb + kbase, ldb, tid);
    };

    load_stage(0); cpa_commit();
    load_stage(1); cpa_commit();
    load_stage(2); cpa_commit();

    const int ar = lane & 15, acg = lane >> 4;
    const int bg = lane >> 3, bl8 = lane & 7;

    for (int t = 0; t < KT; t++) {
        cpa_wait2();          // stage t complete (<=2 newer groups pending)
        __syncthreads();      // publish stage t; all warps done with stage t-1
        if (t + 3 < KT) load_stage(t + 3);   // overwrites buffer (t-1)%4: safe
        cpa_commit();         // keep group accounting uniform

        const uint32_t s = sb + (uint32_t)(t % NSTAGE) * STAGE_B;
        const uint32_t sAh = s, sAl = s + TILE_HB*2;
        const uint32_t sBh = s + 2*TILE_HB*2, sBl = s + 3*TILE_HB*2;

        #pragma unroll
        for (int ks = 0; ks < 2; ks++) {
            uint32_t bh[2][4], bl[2][4];
            #pragma unroll
            for (int nb2 = 0; nb2 < 2; nb2++) {
                int rowb = wcol + nb2*16 + ((bg >> 1) & 1)*8 + bl8;
                int kcb  = ks*16 + (bg & 1)*8;
                uint32_t off = (uint32_t)(rowb*RS + kcb)*2;
                ldm_x4(bh[nb2], sBh + off);
                if (NTERMS == 3) ldm_x4(bl[nb2], sBl + off);
            }
            uint32_t ah[4][4], al[4][4];
            #pragma unroll
            for (int mb = 0; mb < 4; mb++) {
                uint32_t off = (uint32_t)((wrow + mb*16 + ar)*RS + ks*16 + acg*8)*2;
                ldm_x4(ah[mb], sAh + off);
                ldm_x4(al[mb], sAl + off);
            }
            // term-major issue
            #pragma unroll
            for (int mb = 0; mb < 4; mb++)
                #pragma unroll
                for (int nb = 0; nb < 4; nb++)
                    mma_f16(acc[mb][nb], ah[mb], &bh[nb >> 1][(nb & 1)*2]);
            if (NTERMS == 3) {
                #pragma unroll
                for (int mb = 0; mb < 4; mb++)
                    #pragma unroll
                    for (int nb = 0; nb < 4; nb++)
                        mma_f16(acc[mb][nb], ah[mb], &bl[nb >> 1][(nb & 1)*2]);
            }
            #pragma unroll
            for (int mb = 0; mb < 4; mb++)
                #pragma unroll
                for (int nb = 0; nb < 4; nb++)
                    mma_f16(acc[mb][nb], al[mb], &bh[nb >> 1][(nb & 1)*2]);
        }
    }

    // ---- epilogue ----
    const int r0 = lane >> 2, c0 = (lane & 3)*2;
    #pragma unroll
    for (int mb = 0; mb < 4; mb++) {
        #pragma unroll
        for (int nb = 0; nb < 4; nb++) {
            long row = m0 + wrow + mb*16 + r0;
            int  col = n0 + wcol + nb*8 + c0;
            float* a = acc[mb][nb];
            if (C) {
                *(float2*)&C[row*ldc + col]     = make_float2(a[0], a[1]);
                *(float2*)&C[(row+8)*ldc + col] = make_float2(a[2], a[3]);
            }
            if (Coh) {
                uint32_t hi, lo;
                split2h(a[0], a[1], hi, lo);
                *(uint32_t*)&Coh[row*ldco + col] = hi;
                *(uint32_t*)&Col[row*ldco + col] = lo;
                split2h(a[2], a[3], hi, lo);
                *(uint32_t*)&Coh[(row+8)*ldco + col] = hi;
                *(uint32_t*)&Col[(row+8)*ldco + col] = lo;
            }
        }
    }
}

// ---------------- fused one-time converter ----------------
__global__ void cvt_all(const float* __restrict__ in_m, const float* __restrict__ out_m,
                        const float* __restrict__ w3w, const float* __restrict__ w4w,
                        const float* __restrict__ w5w, const float* __restrict__ w3u,
                        const float* __restrict__ w5u)
{
    long p = ((long)blockIdx.x*blockDim.x + threadIdx.x) * 2;
    const long S0 = 1048576, S1 = 2097152, S2 = S1 + 524288, S3 = S2 + 524288,
               S4 = S3 + 524288, S5 = S4 + 262144, S6 = S5 + 262144;
    if (p >= S6) return;
    if (p < S1) {
        // adjacency: hi/lo split
        const float* src = (p < S0) ? in_m : out_m;
        __half *dh = (p < S0) ? g_inM_h : g_outM_h;
        __half *dl = (p < S0) ? g_inM_l : g_outM_l;
        long off = (p < S0) ? p : p - S0;
        float2 v = *(const float2*)&src[off];
        uint32_t h, l;
        split2h(v.x, v.y, h, l);
        *(uint32_t*)&dh[off] = h;
        *(uint32_t*)&dl[off] = l;
    } else {
        // weights: single fp16
        const float* src; __half* dh; long off;
        if      (p < S2) { src = w3w; dh = g_wcat_h;           off = p - S1; }
        else if (p < S3) { src = w4w; dh = g_wcat_h + 524288;  off = p - S2; }
        else if (p < S4) { src = w5w; dh = g_wcat_h + 1048576; off = p - S3; }
        else if (p < S5) { src = w3u; dh = g_w3u_h;            off = p - S4; }
        else             { src = w5u; dh = g_w5u_h;            off = p - S5; }
        float2 v = *(const float2*)&src[off];
        __half2 h = __floats2half2_rn(v.x, v.y);
        *(uint32_t*)&dh[off] = *(uint32_t*)&h;
    }
}

// nodes [b][n][d] fp32 -> ndb hi/lo (straight) + ndT hi/lo (transposed [b][d][n])
__global__ void transpose_cvt(const float* __restrict__ src)
{
    __shared__ float tile[32][33];
    const int b = blockIdx.z;
    const int d0 = blockIdx.x*32, n0 = blockIdx.y*32;
    const float* s = src + (long)b*NN*DD;
    const int tid = threadIdx.x;
    #pragma unroll
    for (int i = 0; i < 4; i++) {
        int p = tid + i*256, n = p >> 5, d = p & 31;
        tile[n][d] = s[(long)(n0+n)*DD + d0 + d];
    }
    __syncthreads();
    #pragma unroll
    for (int i = 0; i < 2; i++) {
        int p = tid + i*256, n = p >> 4, dp = p & 15;
        uint32_t h, l;
        split2h(tile[n][dp*2], tile[n][dp*2+1], h, l);
        long o = ((long)b*NN + n0 + n)*DD + d0 + dp*2;
        *(uint32_t*)&g_ndb_h[o] = h; *(uint32_t*)&g_ndb_l[o] = l;
    }
    #pragma unroll
    for (int i = 0; i < 2; i++) {
        int p = tid + i*256, d = p >> 4, np = p & 15;
        uint32_t h, l;
        split2h(tile[np*2][d], tile[np*2+1][d], h, l);
        long o = ((long)b*DD + d0 + d)*NN + n0 + np*2;
        *(uint32_t*)&g_ndT_h[o] = h; *(uint32_t*)&g_ndT_l[o] = l;
    }
}

// ---------------- elementwise ----------------
__global__ void elem1(const float* __restrict__ b3w, const float* __restrict__ b3u,
                      const float* __restrict__ b4w)
{
    int p = blockIdx.x*blockDim.x + threadIdx.x;
    long i = (long)p*2;
    int row = (int)(i >> 9), e = (int)(i & 511);
    float2 u = *(const float2*)&g_u3[i];
    float2 f = *(const float2*)&g_nodes[i];
    float g3a = g_gates[(long)row*1536 + e],       g3b = g_gates[(long)row*1536 + e + 1];
    float g4a = g_gates[(long)row*1536 + 512 + e], g4b = g_gates[(long)row*1536 + 512 + e + 1];
    float ua = u.x + b3u[e], ub = u.y + b3u[e+1];
    float za = 1.f/(1.f + expf(-(g3a + b3w[e] + ua)));
    float zb = 1.f/(1.f + expf(-(g3b + b3w[e+1] + ub)));
    float ra = 1.f/(1.f + expf(-(g4a + b4w[e] + ua)));
    float rb = 1.f/(1.f + expf(-(g4b + b4w[e+1] + ub)));
    *(float2*)&g_u3[i] = make_float2(za, zb);
    uint32_t h, l;
    split2h(ra*f.x, rb*f.y, h, l);
    *(uint32_t*)&g_rf_h[i] = h;
    *(uint32_t*)&g_rf_l[i] = l;
}

__global__ void elem2(const float* __restrict__ b5w, const float* __restrict__ b5u)
{
    long i = (long)blockIdx.x*blockDim.x + threadIdx.x;
    int row = (int)(i >> 9), e = (int)(i & 511);
    float t  = g_t[i];
    float g5 = g_gates[(long)row*1536 + 1024 + e];
    float hv = tanhf(g5 + b5w[e] + t + b5u[e]);
    float z  = g_u3[i];
    float f  = g_nodes[i];
    g_nodes[i] = (1.f - z)*f + z*hv;
}

__global__ void copy4(const float4* __restrict__ src, float4* __restrict__ dst, int n4)
{
    int i = blockIdx.x*blockDim.x + threadIdx.x;
    if (i < n4) dst[i] = src[i];
}

// ---------------- host launcher ----------------
extern "C" void kernel_launch(void* const* d_in, const int* in_sizes, int n_in,
                              void* d_out, int out_size)
{
    (void)in_sizes; (void)n_in; (void)out_size;
    const float* x     = (const float*)d_in[0];
    const float* in_m  = (const float*)d_in[1];
    const float* out_m = (const float*)d_in[2];
    const float* w3w   = (const float*)d_in[3];
    const float* b3w   = (const float*)d_in[4];
    const float* w3u   = (const float*)d_in[5];
    const float* b3u   = (const float*)d_in[6];
    const float* w4w   = (const float*)d_in[7];
    const float* b4w   = (const float*)d_in[8];
    const float* w5w   = (const float*)d_in[9];
    const float* b5w   = (const float*)d_in[10];
    const float* w5u   = (const float*)d_in[11];
    const float* b5u   = (const float*)d_in[12];
    float* out = (float*)d_out;

    float *nodes, *u3, *tt, *gates;
    cudaGetSymbolAddress((void**)&nodes, g_nodes);
    cudaGetSymbolAddress((void**)&u3,    g_u3);
    cudaGetSymbolAddress((void**)&tt,    g_t);
    cudaGetSymbolAddress((void**)&gates, g_gates);

    __half *inMh,*inMl,*outMh,*outMl,*wcath;
    __half *w3uh,*w5uh,*ndTh,*ndTl,*ndbh,*ndbl;
    __half *ainh,*ainl,*aouth,*aoutl,*rfh,*rfl;
    cudaGetSymbolAddress((void**)&inMh, g_inM_h);  cudaGetSymbolAddress((void**)&inMl, g_inM_l);
    cudaGetSymbolAddress((void**)&outMh,g_outM_h); cudaGetSymbolAddress((void**)&outMl,g_outM_l);
    cudaGetSymbolAddress((void**)&wcath,g_wcat_h);
    cudaGetSymbolAddress((void**)&w3uh, g_w3u_h);
    cudaGetSymbolAddress((void**)&w5uh, g_w5u_h);
    cudaGetSymbolAddress((void**)&ndTh, g_ndT_h);  cudaGetSymbolAddress((void**)&ndTl, g_ndT_l);
    cudaGetSymbolAddress((void**)&ndbh, g_ndb_h);  cudaGetSymbolAddress((void**)&ndbl, g_ndb_l);
    cudaGetSymbolAddress((void**)&ainh, g_ain_h);  cudaGetSymbolAddress((void**)&ainl, g_ain_l);
    cudaGetSymbolAddress((void**)&aouth,g_aout_h); cudaGetSymbolAddress((void**)&aoutl,g_aout_l);
    cudaGetSymbolAddress((void**)&rfh,  g_rf_h);   cudaGetSymbolAddress((void**)&rfl,  g_rf_l);

    cudaFuncSetAttribute(gemm_mma<3>, cudaFuncAttributeMaxDynamicSharedMemorySize, SMEM3);
    cudaFuncSetAttribute(gemm_mma<2>, cudaFuncAttributeMaxDynamicSharedMemorySize, SMEM2);

    const long ND = (long)NN*DD;     // 524288
    const int  BIG = 1 << 30;

    copy4<<<(BB*NN*DD/4 + 255)/256, 256>>>((const float4*)x, (float4*)nodes, BB*NN*DD/4);
    cvt_all<<<8192, 256>>>(in_m, out_m, w3w, w4w, w5w, w3u, w5u);

    for (int step = 0; step < TIME_STEP; step++) {
        transpose_cvt<<<dim3(DD/32, NN/32, BB), 256>>>(nodes);

        // fused a_in + a_out: 3-term (B = nodes, hi/lo). z>=16 -> out_matrix.
        dim3 gp(DD/128, NN/128, 2*BB);
        gemm_mma<3><<<gp, NT, SMEM3>>>(inMh, inMl, outMh, outMl, BIG, NN, 1,
                                       ndTh, ndTl, NN,
                                       nullptr, 0,
                                       ainh, ainl, aouth, aoutl, DD,
                                       NN, 0L, ND, 0L, ND);

        // fused gates: 2-term. [ain|aout] @ wcat^T, M=16384, N=1536, K=1024
        dim3 gg3(3*DD/128, ROWS/128, 1);   // (12, 128)
        gemm_mma<2><<<gg3, NT, SMEM2>>>(ainh, ainl, aouth, aoutl, DD, DD, 0,
                                        wcath, nullptr, 2*DD,
                                        gates, 3*DD,
                                        nullptr, nullptr, nullptr, nullptr, 0,
                                        2*DD, 0L, 0L, 0L, 0L);

        // u3 = nodes @ w3u^T: 2-term
        dim3 gg(DD/128, ROWS/128, 1);
        gemm_mma<2><<<gg, NT, SMEM2>>>(ndbh, ndbl, ndbh, ndbl, BIG, DD, 0,
                                       w3uh, nullptr, DD,
                                       u3, DD,
                                       nullptr, nullptr, nullptr, nullptr, 0,
                                       DD, 0L, 0L, 0L, 0L);

        elem1<<<ROWS*DD/2/256, 256>>>(b3w, b3u, b4w);

        // t = (rv*f) @ w5u^T: 2-term
        gemm_mma<2><<<gg, NT, SMEM2>>>(rfh, rfl, rfh, rfl, BIG, DD, 0,
                                       w5uh, nullptr, DD,
                                       tt, DD,
                                       nullptr, nullptr, nullptr, nullptr, 0,
                                       DD, 0L, 0L, 0L, 0L);

        elem2<<<ROWS*DD/256, 256>>>(b5w, b5u);
    }

    copy4<<<(BB*NN*DD/4 + 255)/256, 256>>>((const float4*)nodes, (float4*)out, BB*NN*DD/4);
    copy4<<<(NN*NN/4 + 255)/256, 256>>>((const float4*)in_m,
                                        (float4*)(out + (long)BB*NN*DD), NN*NN/4);
}

// round 16
// speedup vs baseline: 2.0469x; 1.1151x over previous
#include <cuda_runtime.h>
#include <cuda_fp16.h>
#include <cstdint>
#include <math.h>

#define BB 16
#define NN 1024
#define DD 512
#define ROWS (BB*NN)          // 16384
#define TIME_STEP 3

// ---------------- fp32 scratch ----------------
__device__ float g_nodes[BB*NN*DD];
__device__ float g_u3   [BB*NN*DD];          // u3, then zv
__device__ float g_t    [BB*NN*DD];          // (rv*f)@w5u^T
__device__ float g_gates[BB*NN*3*DD];        // [16384][1536]

// ---------------- fp16 operand buffers ----------------
__device__ __half g_inM_h [NN*NN], g_inM_l [NN*NN];
__device__ __half g_outM_h[NN*NN], g_outM_l[NN*NN];
__device__ __half g_wcat_h[3*DD*2*DD];               // [1536][1024] single
__device__ __half g_w3u_h[DD*DD];
__device__ __half g_w5u_h[DD*DD];
__device__ __half g_ndT_h[BB*DD*NN];                 // [b][d][n] single
__device__ __half g_ndb_h[BB*NN*DD], g_ndb_l[BB*NN*DD];   // [b][n][d] hi/lo
__device__ __half g_ain_h[BB*NN*DD], g_ain_l[BB*NN*DD];
__device__ __half g_aout_h[BB*NN*DD], g_aout_l[BB*NN*DD];
__device__ __half g_rf_h [BB*NN*DD], g_rf_l [BB*NN*DD];

// ---------------- helpers ----------------
__device__ __forceinline__ uint32_t smem_u32(const void* p) {
    uint32_t a;
    asm("{ .reg .u64 t; cvta.to.shared.u64 t, %1; cvt.u32.u64 %0, t; }" : "=r"(a) : "l"(p));
    return a;
}
__device__ __forceinline__ void split2h(float x, float y, uint32_t& hi, uint32_t& lo) {
    __half2 h = __floats2half2_rn(x, y);   // low=x, high=y
    float rx = x - __half2float(__low2half(h));
    float ry = y - __half2float(__high2half(h));
    __half2 l = __floats2half2_rn(rx, ry);
    hi = *(uint32_t*)&h; lo = *(uint32_t*)&l;
}
__device__ __forceinline__ void cpa16(uint32_t s, const void* g) {
    asm volatile("cp.async.cg.shared.global [%0], [%1], 16;" :: "r"(s), "l"(g));
}
__device__ __forceinline__ void cpa_commit() {
    asm volatile("cp.async.commit_group;" ::: "memory");
}
__device__ __forceinline__ void cpa_wait2() {
    asm volatile("cp.async.wait_group 2;" ::: "memory");
}
__device__ __forceinline__ void ldm_x4(uint32_t* r, uint32_t addr) {
    asm volatile("ldmatrix.sync.aligned.m8n8.x4.shared.b16 {%0,%1,%2,%3}, [%4];"
                 : "=r"(r[0]), "=r"(r[1]), "=r"(r[2]), "=r"(r[3]) : "r"(addr));
}
__device__ __forceinline__ void mma_f16(float* d, const uint32_t* a, const uint32_t* b) {
    asm volatile("mma.sync.aligned.m16n8k16.row.col.f32.f16.f16.f32 "
                 "{%0,%1,%2,%3}, {%4,%5,%6,%7}, {%8,%9}, {%0,%1,%2,%3};"
                 : "+f"(d[0]), "+f"(d[1]), "+f"(d[2]), "+f"(d[3])
                 : "r"(a[0]), "r"(a[1]), "r"(a[2]), "r"(a[3]), "r"(b[0]), "r"(b[1]));
}

// ======================= fp16 2-term split mma.sync GEMM =======================
// C = Ahi*B + Alo*B   (A hi/lo split, B single fp16)
// 128x128 CTA, 256 threads, warp grid 2x4 (warp tile 64x32), term-major issue.
// msel=0: A' = A for k<ksplit else A2 at k-ksplit; batch z via aB/bB/cB/coB.
// msel=1: matrix pair (A vs A2) chosen by z>=16; batch = z&15; epilogue goes
//         to (Coh,Col) for z<16 and (Co2h,Co2l) for z>=16. ksplit unused.
#define KC 32
#define RS 40                      // smem row stride in halves (80B, 16B-aligned)
#define TILE_HB (128*RS)           // halves per tile (5120)
#define NSTAGE 4
#define NT 256
#define GEMM_SMEM (NSTAGE*3*TILE_HB*2)   // 122880

__device__ __forceinline__ void load_tile(uint32_t sbase, const __half* g,
                                          int ld, int tid)
{
    int row = tid >> 2, cb = tid & 3;      // 256 threads: 2x 16B per tile
    cpa16(sbase + (uint32_t)(row*RS + cb*8)*2, g + (long)row*ld + cb*8);
    cpa16(sbase + (uint32_t)((row+64)*RS + cb*8)*2, g + (long)(row+64)*ld + cb*8);
}

__global__ __launch_bounds__(NT, 1)
void gemm_mma(const __half* __restrict__ Ah, const __half* __restrict__ Al,
              const __half* __restrict__ A2h, const __half* __restrict__ A2l,
              int ksplit, int lda, int msel,
              const __half* __restrict__ Bh, int ldb,
              float* __restrict__ C, int ldc,
              __half* __restrict__ Coh, __half* __restrict__ Col,
              __half* __restrict__ Co2h, __half* __restrict__ Co2l,
              int ldco,
              int Kd, long aB, long bB, long cB, long coB)
{
    constexpr uint32_t STAGE_B = 3u * TILE_HB * 2;

    extern __shared__ char smem[];
    const uint32_t sb = smem_u32(smem);

    long z = blockIdx.z;
    if (msel) {
        if (z >= 16) { Ah = A2h; Al = A2l; Coh = Co2h; Col = Co2l; z -= 16; }
        A2h = Ah; A2l = Al;
        ksplit = 1 << 30;
    }
    Ah += z*aB; Al += z*aB; A2h += z*aB; A2l += z*aB;
    Bh += z*bB;
    if (C)   C   += z*cB;
    if (Coh) { Coh += z*coB; Col += z*coB; }

    const int tid = threadIdx.x;
    const int wid = tid >> 5, lane = tid & 31;
    const int m0 = blockIdx.y * 128, n0 = blockIdx.x * 128;
    const int wrow = (wid & 1) * 64;       // 2 warp-rows x 64
    const int wcol = (wid >> 1) * 32;      // 4 warp-cols x 32

    float acc[4][4][4];                    // [mb][nb][frag] : 64x32 warp tile
    #pragma unroll
    for (int i = 0; i < 4; i++)
        #pragma unroll
        for (int j = 0; j < 4; j++)
            #pragma unroll
            for (int k = 0; k < 4; k++) acc[i][j][k] = 0.f;

    const int KT = Kd / KC;

    auto load_stage = [&](int t) {
        int kbase = t * KC;
        const __half *pah = Ah, *pal = Al;
        int ka = kbase;
        if (kbase >= ksplit) { pah = A2h; pal = A2l; ka -= ksplit; }
        uint32_t s = sb + (uint32_t)(t % NSTAGE) * STAGE_B;
        load_tile(s,               pah + (long)m0*lda + ka,    lda, tid);
        load_tile(s + TILE_HB*2,   pal + (long)m0*lda + ka,    lda, tid);
        load_tile(s + 2*TILE_HB*2, Bh  + (long)n0*ldb + kbase, ldb, tid);
    };

    load_stage(0); cpa_commit();
    load_stage(1); cpa_commit();
    load_stage(2); cpa_commit();

    const int ar = lane & 15, acg = lane >> 4;
    const int bg = lane >> 3, bl8 = lane & 7;

    for (int t = 0; t < KT; t++) {
        cpa_wait2();          // stage t complete (<=2 newer groups pending)
        __syncthreads();      // publish stage t; all warps done with stage t-1
        if (t + 3 < KT) load_stage(t + 3);   // overwrites buffer (t-1)%4: safe
        cpa_commit();         // keep group accounting uniform

        const uint32_t s = sb + (uint32_t)(t % NSTAGE) * STAGE_B;
        const uint32_t sAh = s, sAl = s + TILE_HB*2;
        const uint32_t sBh = s + 2*TILE_HB*2;

        #pragma unroll
        for (int ks = 0; ks < 2; ks++) {
            uint32_t bh[2][4];
            #pragma unroll
            for (int nb2 = 0; nb2 < 2; nb2++) {
                int rowb = wcol + nb2*16 + ((bg >> 1) & 1)*8 + bl8;
                int kcb  = ks*16 + (bg & 1)*8;
                uint32_t off = (uint32_t)(rowb*RS + kcb)*2;
                ldm_x4(bh[nb2], sBh + off);
            }
            uint32_t ah[4][4], al[4][4];
            #pragma unroll
            for (int mb = 0; mb < 4; mb++) {
                uint32_t off = (uint32_t)((wrow + mb*16 + ar)*RS + ks*16 + acg*8)*2;
                ldm_x4(ah[mb], sAh + off);
                ldm_x4(al[mb], sAl + off);
            }
            // term-major issue
            #pragma unroll
            for (int mb = 0; mb < 4; mb++)
                #pragma unroll
                for (int nb = 0; nb < 4; nb++)
                    mma_f16(acc[mb][nb], ah[mb], &bh[nb >> 1][(nb & 1)*2]);
            #pragma unroll
            for (int mb = 0; mb < 4; mb++)
                #pragma unroll
                for (int nb = 0; nb < 4; nb++)
                    mma_f16(acc[mb][nb], al[mb], &bh[nb >> 1][(nb & 1)*2]);
        }
    }

    // ---- epilogue ----
    const int r0 = lane >> 2, c0 = (lane & 3)*2;
    #pragma unroll
    for (int mb = 0; mb < 4; mb++) {
        #pragma unroll
        for (int nb = 0; nb < 4; nb++) {
            long row = m0 + wrow + mb*16 + r0;
            int  col = n0 + wcol + nb*8 + c0;
            float* a = acc[mb][nb];
            if (C) {
                *(float2*)&C[row*ldc + col]     = make_float2(a[0], a[1]);
                *(float2*)&C[(row+8)*ldc + col] = make_float2(a[2], a[3]);
            }
            if (Coh) {
                uint32_t hi, lo;
                split2h(a[0], a[1], hi, lo);
                *(uint32_t*)&Coh[row*ldco + col] = hi;
                *(uint32_t*)&Col[row*ldco + col] = lo;
                split2h(a[2], a[3], hi, lo);
                *(uint32_t*)&Coh[(row+8)*ldco + col] = hi;
                *(uint32_t*)&Col[(row+8)*ldco + col] = lo;
            }
        }
    }
}

// ---------------- fused one-time converter ----------------
__global__ void cvt_all(const float* __restrict__ in_m, const float* __restrict__ out_m,
                        const float* __restrict__ w3w, const float* __restrict__ w4w,
                        const float* __restrict__ w5w, const float* __restrict__ w3u,
                        const float* __restrict__ w5u)
{
    long p = ((long)blockIdx.x*blockDim.x + threadIdx.x) * 2;
    const long S0 = 1048576, S1 = 2097152, S2 = S1 + 524288, S3 = S2 + 524288,
               S4 = S3 + 524288, S5 = S4 + 262144, S6 = S5 + 262144;
    if (p >= S6) return;
    if (p < S1) {
        // adjacency: hi/lo split
        const float* src = (p < S0) ? in_m : out_m;
        __half *dh = (p < S0) ? g_inM_h : g_outM_h;
        __half *dl = (p < S0) ? g_inM_l : g_outM_l;
        long off = (p < S0) ? p : p - S0;
        float2 v = *(const float2*)&src[off];
        uint32_t h, l;
        split2h(v.x, v.y, h, l);
        *(uint32_t*)&dh[off] = h;
        *(uint32_t*)&dl[off] = l;
    } else {
        // weights: single fp16
        const float* src; __half* dh; long off;
        if      (p < S2) { src = w3w; dh = g_wcat_h;           off = p - S1; }
        else if (p < S3) { src = w4w; dh = g_wcat_h + 524288;  off = p - S2; }
        else if (p < S4) { src = w5w; dh = g_wcat_h + 1048576; off = p - S3; }
        else if (p < S5) { src = w3u; dh = g_w3u_h;            off = p - S4; }
        else             { src = w5u; dh = g_w5u_h;            off = p - S5; }
        float2 v = *(const float2*)&src[off];
        __half2 h = __floats2half2_rn(v.x, v.y);
        *(uint32_t*)&dh[off] = *(uint32_t*)&h;
    }
}

// nodes [b][n][d] fp32 -> ndb hi/lo (straight) + ndT single (transposed [b][d][n])
__global__ void transpose_cvt(const float* __restrict__ src)
{
    __shared__ float tile[32][33];
    const int b = blockIdx.z;
    const int d0 = blockIdx.x*32, n0 = blockIdx.y*32;
    const float* s = src + (long)b*NN*DD;
    const int tid = threadIdx.x;
    #pragma unroll
    for (int i = 0; i < 4; i++) {
        int p = tid + i*256, n = p >> 5, d = p & 31;
        tile[n][d] = s[(long)(n0+n)*DD + d0 + d];
    }
    __syncthreads();
    #pragma unroll
    for (int i = 0; i < 2; i++) {
        int p = tid + i*256, n = p >> 4, dp = p & 15;
        uint32_t h, l;
        split2h(tile[n][dp*2], tile[n][dp*2+1], h, l);
        long o = ((long)b*NN + n0 + n)*DD + d0 + dp*2;
        *(uint32_t*)&g_ndb_h[o] = h; *(uint32_t*)&g_ndb_l[o] = l;
    }
    #pragma unroll
    for (int i = 0; i < 2; i++) {
        int p = tid + i*256, d = p >> 4, np = p & 15;
        __half2 h = __floats2half2_rn(tile[np*2][d], tile[np*2+1][d]);
        long o = ((long)b*DD + d0 + d)*NN + n0 + np*2;
        *(uint32_t*)&g_ndT_h[o] = *(uint32_t*)&h;
    }
}

// ---------------- elementwise ----------------
__global__ void elem1(const float* __restrict__ b3w, const float* __restrict__ b3u,
                      const float* __restrict__ b4w)
{
    int p = blockIdx.x*blockDim.x + threadIdx.x;
    long i = (long)p*2;
    int row = (int)(i >> 9), e = (int)(i & 511);
    float2 u = *(const float2*)&g_u3[i];
    float2 f = *(const float2*)&g_nodes[i];
    float g3a = g_gates[(long)row*1536 + e],       g3b = g_gates[(long)row*1536 + e + 1];
    float g4a = g_gates[(long)row*1536 + 512 + e], g4b = g_gates[(long)row*1536 + 512 + e + 1];
    float ua = u.x + b3u[e], ub = u.y + b3u[e+1];
    float za = 1.f/(1.f + expf(-(g3a + b3w[e] + ua)));
    float zb = 1.f/(1.f + expf(-(g3b + b3w[e+1] + ub)));
    float ra = 1.f/(1.f + expf(-(g4a + b4w[e] + ua)));
    float rb = 1.f/(1.f + expf(-(g4b + b4w[e+1] + ub)));
    *(float2*)&g_u3[i] = make_float2(za, zb);
    uint32_t h, l;
    split2h(ra*f.x, rb*f.y, h, l);
    *(uint32_t*)&g_rf_h[i] = h;
    *(uint32_t*)&g_rf_l[i] = l;
}

__global__ void elem2(const float* __restrict__ b5w, const float* __restrict__ b5u,
                      float* __restrict__ dst)
{
    long i = (long)blockIdx.x*blockDim.x + threadIdx.x;
    int row = (int)(i >> 9), e = (int)(i & 511);
    float t  = g_t[i];
    float g5 = g_gates[(long)row*1536 + 1024 + e];
    float hv = tanhf(g5 + b5w[e] + t + b5u[e]);
    float z  = g_u3[i];
    float f  = g_nodes[i];
    dst[i] = (1.f - z)*f + z*hv;
}

__global__ void copy4(const float4* __restrict__ src, float4* __restrict__ dst, int n4)
{
    int i = blockIdx.x*blockDim.x + threadIdx.x;
    if (i < n4) dst[i] = src[i];
}

// ---------------- host launcher ----------------
extern "C" void kernel_launch(void* const* d_in, const int* in_sizes, int n_in,
                              void* d_out, int out_size)
{
    (void)in_sizes; (void)n_in; (void)out_size;
    const float* x     = (const float*)d_in[0];
    const float* in_m  = (const float*)d_in[1];
    const float* out_m = (const float*)d_in[2];
    const float* w3w   = (const float*)d_in[3];
    const float* b3w   = (const float*)d_in[4];
    const float* w3u   = (const float*)d_in[5];
    const float* b3u   = (const float*)d_in[6];
    const float* w4w   = (const float*)d_in[7];
    const float* b4w   = (const float*)d_in[8];
    const float* w5w   = (const float*)d_in[9];
    const float* b5w   = (const float*)d_in[10];
    const float* w5u   = (const float*)d_in[11];
    const float* b5u   = (const float*)d_in[12];
    float* out = (float*)d_out;

    float *nodes, *u3, *tt, *gates;
    cudaGetSymbolAddress((void**)&nodes, g_nodes);
    cudaGetSymbolAddress((void**)&u3,    g_u3);
    cudaGetSymbolAddress((void**)&tt,    g_t);
    cudaGetSymbolAddress((void**)&gates, g_gates);

    __half *inMh,*inMl,*outMh,*outMl,*wcath;
    __half *w3uh,*w5uh,*ndTh,*ndbh,*ndbl;
    __half *ainh,*ainl,*aouth,*aoutl,*rfh,*rfl;
    cudaGetSymbolAddress((void**)&inMh, g_inM_h);  cudaGetSymbolAddress((void**)&inMl, g_inM_l);
    cudaGetSymbolAddress((void**)&outMh,g_outM_h); cudaGetSymbolAddress((void**)&outMl,g_outM_l);
    cudaGetSymbolAddress((void**)&wcath,g_wcat_h);
    cudaGetSymbolAddress((void**)&w3uh, g_w3u_h);
    cudaGetSymbolAddress((void**)&w5uh, g_w5u_h);
    cudaGetSymbolAddress((void**)&ndTh, g_ndT_h);
    cudaGetSymbolAddress((void**)&ndbh, g_ndb_h);  cudaGetSymbolAddress((void**)&ndbl, g_ndb_l);
    cudaGetSymbolAddress((void**)&ainh, g_ain_h);  cudaGetSymbolAddress((void**)&ainl, g_ain_l);
    cudaGetSymbolAddress((void**)&aouth,g_aout_h); cudaGetSymbolAddress((void**)&aoutl,g_aout_l);
    cudaGetSymbolAddress((void**)&rfh,  g_rf_h);   cudaGetSymbolAddress((void**)&rfl,  g_rf_l);

    cudaFuncSetAttribute(gemm_mma, cudaFuncAttributeMaxDynamicSharedMemorySize, GEMM_SMEM);

    const long ND = (long)NN*DD;     // 524288
    const int  BIG = 1 << 30;

    copy4<<<(BB*NN*DD/4 + 255)/256, 256>>>((const float4*)x, (float4*)nodes, BB*NN*DD/4);
    cvt_all<<<8192, 256>>>(in_m, out_m, w3w, w4w, w5w, w3u, w5u);

    for (int step = 0; step < TIME_STEP; step++) {
        transpose_cvt<<<dim3(DD/32, NN/32, BB), 256>>>(nodes);

        // fused a_in + a_out: A = adjacency (hi/lo), B = ndT single.
        // z>=16 -> out_matrix; epilogue -> ain / aout hi/lo.
        dim3 gp(DD/128, NN/128, 2*BB);
        gemm_mma<<<gp, NT, GEMM_SMEM>>>(inMh, inMl, outMh, outMl, BIG, NN, 1,
                                        ndTh, NN,
                                        nullptr, 0,
                                        ainh, ainl, aouth, aoutl, DD,
                                        NN, 0L, ND, 0L, ND);

        // fused gates: [ain|aout] @ wcat^T, M=16384, N=1536, K=1024
        dim3 gg3(3*DD/128, ROWS/128, 1);   // (12, 128)
        gemm_mma<<<gg3, NT, GEMM_SMEM>>>(ainh, ainl, aouth, aoutl, DD, DD, 0,
                                         wcath, 2*DD,
                                         gates, 3*DD,
                                         nullptr, nullptr, nullptr, nullptr, 0,
                                         2*DD, 0L, 0L, 0L, 0L);

        // u3 = nodes @ w3u^T
        dim3 gg(DD/128, ROWS/128, 1);
        gemm_mma<<<gg, NT, GEMM_SMEM>>>(ndbh, ndbl, ndbh, ndbl, BIG, DD, 0,
                                        w3uh, DD,
                                        u3, DD,
                                        nullptr, nullptr, nullptr, nullptr, 0,
                                        DD, 0L, 0L, 0L, 0L);

        elem1<<<ROWS*DD/2/256, 256>>>(b3w, b3u, b4w);

        // t = (rv*f) @ w5u^T
        gemm_mma<<<gg, NT, GEMM_SMEM>>>(rfh, rfl, rfh, rfl, BIG, DD, 0,
                                        w5uh, DD,
                                        tt, DD,
                                        nullptr, nullptr, nullptr, nullptr, 0,
                                        DD, 0L, 0L, 0L, 0L);

        // last step writes nodes directly into d_out
        float* dst = (step == TIME_STEP-1) ? out : nodes;
        elem2<<<ROWS*DD/256, 256>>>(b5w, b5u, dst);
    }

    copy4<<<(NN*NN/4 + 255)/256, 256>>>((const float4*)in_m,
                                        (float4*)(out + (long)BB*NN*DD), NN*NN/4);
}